// round 12
// baseline (speedup 1.0000x reference)
#include <cuda_runtime.h>

#define NT     512
#define TLEN   512
#define LD     36     // padded leading dim, 32-col matrices
#define LDA    68     // Y-augmented GJ matrix leading dim (32x64)
#define LDS2   52     // S-augmented GJ matrix leading dim (16x48)
#define LDCT   20     // C^T / CA^T / CQC leading dim
#define LDK    20     // KT2 leading dim
#define MAXB   128

// scratch: smoother gains & predicted stats produced in forward pass
__device__ float g_Y [MAXB * TLEN * 1024];
__device__ float g_Nm[MAXB * TLEN * 1024];
__device__ float g_zp[MAXB * TLEN * 32];

// ---- shared memory layout (float offsets) ----
#define O_SAM  0
#define O_SBM  8192
#define O_SCM  16384
#define O_A    20480   // 32xLD A_t
#define O_ATR  21632   // 32xLD A_t^T
#define O_CM   22784   // 16xLD C_t
#define O_CTR  23360   // 32xLDCT C_t^T
#define O_ZC   24000   // 32xLD covariance state (filtered / Ps)
#define O_TMP  25152   // 32xLD B mixture (F2+: CN in rows 0-15)
#define O_PP   26304   // 32xLD Ppred
#define O_CPM  27456   // 16xLD M
#define O_AUG0 28032   // 32xLDA Y-GJ buffer 0
#define O_AUG1 30208   // 32xLDA Y-GJ buffer 1 (bwd: W)
#define O_AGS0 32384   // 16xLDS2 S-GJ buffer 0
#define O_AGS1 33216   // 16xLDS2 S-GJ buffer 1
#define O_KT2  34048   // 32xLDK Kg (row i, col r)
#define O_FCS  34688   // 2 x 1152 filtered cov (parity)
#define O_FMS  36992   // 2 x 32
#define O_YB   37056   // 2 x 1152 Y (parity)
#define O_YT   39360   // 2 x 1152 Y^T (parity)
#define O_NB   41664   // 2 x 1152 N (parity)
#define O_ZPS  43968   // 2 x 32 zpred (parity)
#define O_ZM   44032   // 32
#define O_ZM2  44064   // 32
#define O_AL   44096   // 2 x 8
#define O_SU   44112   // 2 x 32
#define O_SA   44176   // 2 x 16
#define O_AP   44208   // 16
#define O_DZ   44224   // 32
#define O_QD   44256   // 32
#define O_RD   44288   // 16
#define O_CAT  44304   // 32xLDCT  CA^T
#define O_CQC  44944   // 16xLDCT  C diag(q) C^T
#define SMEM_FLOATS 45264

#define BAR_A() asm volatile("bar.sync 1, 256;" ::: "memory")
#define BAR_B() asm volatile("bar.sync 2, 256;" ::: "memory")

__device__ __forceinline__ float4 f4fma(float s, float4 b, float4 a) {
    return make_float4(fmaf(s,b.x,a.x), fmaf(s,b.y,a.y), fmaf(s,b.z,a.z), fmaf(s,b.w,a.w));
}
__device__ __forceinline__ float4 f4scale(float4 a, float s) {
    return make_float4(a.x*s, a.y*s, a.z*s, a.w*s);
}
#define FMA4S(acc, s, b)                                                      \
    acc.x = fmaf((s), (b).x, acc.x); acc.y = fmaf((s), (b).y, acc.y);         \
    acc.z = fmaf((s), (b).z, acc.z); acc.w = fmaf((s), (b).w, acc.w);
#define FMA4L(s4, m4, v4)                                                     \
    s4.x = fmaf(m4.x, v4.x, s4.x); s4.y = fmaf(m4.y, v4.y, s4.y);             \
    s4.z = fmaf(m4.z, v4.z, s4.z); s4.w = fmaf(m4.w, v4.w, s4.w);

__device__ __forceinline__ float4 mm4(const float* __restrict__ rowA,
                                      const float* __restrict__ matB,
                                      const int ldB, const int jj) {
    float4 a0 = make_float4(0.f,0.f,0.f,0.f);
    float4 a1 = make_float4(0.f,0.f,0.f,0.f);
    #pragma unroll
    for (int k0 = 0; k0 < 32; k0 += 8) {
        float4 x = *(const float4*)(rowA + k0);
        float4 y = *(const float4*)(rowA + k0 + 4);
        const float* Bp = matB + k0 * ldB + jj;
        float4 b;
        b = *(const float4*)(Bp);           FMA4S(a0, x.x, b);
        b = *(const float4*)(Bp + ldB);     FMA4S(a1, x.y, b);
        b = *(const float4*)(Bp + 2*ldB);   FMA4S(a0, x.z, b);
        b = *(const float4*)(Bp + 3*ldB);   FMA4S(a1, x.w, b);
        b = *(const float4*)(Bp + 4*ldB);   FMA4S(a0, y.x, b);
        b = *(const float4*)(Bp + 5*ldB);   FMA4S(a1, y.y, b);
        b = *(const float4*)(Bp + 6*ldB);   FMA4S(a0, y.z, b);
        b = *(const float4*)(Bp + 7*ldB);   FMA4S(a1, y.w, b);
    }
    return make_float4(a0.x + a1.x, a0.y + a1.y, a0.z + a1.z, a0.w + a1.w);
}

// two rows x 4 cols: B loads shared between the rows (backward pass)
__device__ __forceinline__ void mm24(const float* __restrict__ rA0,
                                     const float* __restrict__ rA1,
                                     const float* __restrict__ matB,
                                     const int ldB, const int jj,
                                     float4& o0, float4& o1) {
    float4 a0 = make_float4(0.f,0.f,0.f,0.f);
    float4 a1 = make_float4(0.f,0.f,0.f,0.f);
    float4 c0 = make_float4(0.f,0.f,0.f,0.f);
    float4 c1 = make_float4(0.f,0.f,0.f,0.f);
    #pragma unroll
    for (int k0 = 0; k0 < 32; k0 += 4) {
        float4 x = *(const float4*)(rA0 + k0);
        float4 y = *(const float4*)(rA1 + k0);
        const float* Bp = matB + k0 * ldB + jj;
        float4 b;
        b = *(const float4*)(Bp);         FMA4S(a0, x.x, b); FMA4S(c0, y.x, b);
        b = *(const float4*)(Bp + ldB);   FMA4S(a1, x.y, b); FMA4S(c1, y.y, b);
        b = *(const float4*)(Bp + 2*ldB); FMA4S(a0, x.z, b); FMA4S(c0, y.z, b);
        b = *(const float4*)(Bp + 3*ldB); FMA4S(a1, x.w, b); FMA4S(c1, y.w, b);
    }
    o0 = make_float4(a0.x+a1.x, a0.y+a1.y, a0.z+a1.z, a0.w+a1.w);
    o1 = make_float4(c0.x+c1.x, c0.y+c1.y, c0.z+c1.z, c0.w+c1.w);
}

// ---- 4-pivot Gauss-Jordan block state ----
struct GJ4 {
    float inv0, inv1, inv2, inv3;
    float P10, P20, P30, a21, a31, a32;
    float c0, c1, c2, c3;
    int p0, gi;
};
__device__ __forceinline__ GJ4 gj4_pre(const float* __restrict__ Asrc, int gi,
                                       int p0, int lda) {
    GJ4 s; s.p0 = p0; s.gi = gi;
    const float4 R0 = *(const float4*)(Asrc + (p0+0)*lda + p0);
    const float4 R1 = *(const float4*)(Asrc + (p0+1)*lda + p0);
    const float4 R2 = *(const float4*)(Asrc + (p0+2)*lda + p0);
    const float4 R3 = *(const float4*)(Asrc + (p0+3)*lda + p0);
    const float4 Ci = *(const float4*)(Asrc + gi*lda + p0);
    s.inv0 = __fdividef(1.f, R0.x);
    float u01 = R0.y*s.inv0, u02 = R0.z*s.inv0, u03 = R0.w*s.inv0;
    s.P10 = R1.x;
    float a11 = fmaf(-R1.x, u01, R1.y);  s.inv1 = __fdividef(1.f, a11);
    float a12 = fmaf(-R1.x, u02, R1.z), a13 = fmaf(-R1.x, u03, R1.w);
    float v12 = a12*s.inv1, v13 = a13*s.inv1;
    s.P20 = R2.x;
    s.a21 = fmaf(-R2.x, u01, R2.y);
    float a22 = fmaf(-s.a21, v12, fmaf(-R2.x, u02, R2.z));
    s.inv2 = __fdividef(1.f, a22);
    float a23 = fmaf(-s.a21, v13, fmaf(-R2.x, u03, R2.w));
    float w23 = a23*s.inv2;
    s.P30 = R3.x;
    s.a31 = fmaf(-R3.x, u01, R3.y);
    s.a32 = fmaf(-s.a31, v12, fmaf(-R3.x, u02, R3.z));
    float a33 = fmaf(-s.a32, w23, fmaf(-s.a31, v13, fmaf(-R3.x, u03, R3.w)));
    s.inv3 = __fdividef(1.f, a33);
    s.c0 = Ci.x;
    s.c1 = (gi==p0)   ? u01 : fmaf(-s.c0, u01, Ci.y);
    float c2t = (gi==p0)   ? u02 : fmaf(-s.c0, u02, Ci.z);
    s.c2 = (gi==p0+1) ? v12 : fmaf(-s.c1, v12, c2t);
    float c3t = (gi==p0)   ? u03 : fmaf(-s.c0, u03, Ci.w);
    float c3u = (gi==p0+1) ? v13 : fmaf(-s.c1, v13, c3t);
    s.c3 = (gi==p0+2) ? w23 : fmaf(-s.c2, w23, c3u);
    return s;
}
__device__ __forceinline__ float4 gj4_col4(const GJ4& s, const float* __restrict__ Asrc,
                                           int jj, int lda) {
    const int p0 = s.p0, gi = s.gi;
    float4 m0 = *(const float4*)(Asrc + (p0+0)*lda + jj);
    float4 m1 = *(const float4*)(Asrc + (p0+1)*lda + jj);
    float4 m2 = *(const float4*)(Asrc + (p0+2)*lda + jj);
    float4 m3 = *(const float4*)(Asrc + (p0+3)*lda + jj);
    float4 mi = *(const float4*)(Asrc + gi*lda + jj);
    float4 r0 = f4scale(m0, s.inv0);
    float4 E  = (gi==p0)   ? r0 : f4fma(-s.c0, r0, mi);
    float4 t1 = f4fma(-s.P10, r0, m1);
    float4 r1 = f4scale(t1, s.inv1);
    E = (gi==p0+1) ? r1 : f4fma(-s.c1, r1, E);
    float4 t2 = f4fma(-s.a21, r1, f4fma(-s.P20, r0, m2));
    float4 r2 = f4scale(t2, s.inv2);
    E = (gi==p0+2) ? r2 : f4fma(-s.c2, r2, E);
    float4 t3 = f4fma(-s.a32, r2, f4fma(-s.a31, r1, f4fma(-s.P30, r0, m3)));
    float4 r3 = f4scale(t3, s.inv3);
    E = (gi==p0+3) ? r3 : f4fma(-s.c3, r3, E);
    return E;
}

__global__ __launch_bounds__(NT, 1)
void lgssm_kernel(const float* __restrict__ g_a,   const float* __restrict__ g_alpha,
                  const float* __restrict__ g_u,   const float* __restrict__ g_A,
                  const float* __restrict__ g_B,   const float* __restrict__ g_C,
                  const float* __restrict__ g_lQ,  const float* __restrict__ g_lR,
                  const float* __restrict__ g_z0m, const float* __restrict__ g_z0lv,
                  float* __restrict__ out)
{
    extern __shared__ float sh[];
    float* sAm  = sh + O_SAM;
    float* sBm  = sh + O_SBM;
    float* sCm  = sh + O_SCM;
    float* pA   = sh + O_A;
    float* pAtr = sh + O_ATR;
    float* pCm  = sh + O_CM;
    float* pCtr = sh + O_CTR;
    float* zc   = sh + O_ZC;
    float* tmpM = sh + O_TMP;
    float* pPp  = sh + O_PP;
    float* pCPm = sh + O_CPM;
    float* aug0 = sh + O_AUG0;
    float* aug1 = sh + O_AUG1;
    float* augS0= sh + O_AGS0;
    float* augS1= sh + O_AGS1;
    float* KT2  = sh + O_KT2;
    float* fcS  = sh + O_FCS;
    float* fmS  = sh + O_FMS;
    float* Ybuf = sh + O_YB;
    float* YtrB = sh + O_YT;
    float* NbS  = sh + O_NB;
    float* zpS  = sh + O_ZPS;
    float* zm   = sh + O_ZM;
    float* zm2  = sh + O_ZM2;
    float* alB  = sh + O_AL;
    float* suB  = sh + O_SU;
    float* saB  = sh + O_SA;
    float* apred= sh + O_AP;
    float* dz   = sh + O_DZ;
    float* qd   = sh + O_QD;
    float* rd   = sh + O_RD;
    float* CAtr = sh + O_CAT;
    float* CQC  = sh + O_CQC;

    const int tid = threadIdx.x;
    const int b   = blockIdx.x;
    const int i4  = tid >> 3;          // 0..31 for tid<256
    const int j4  = (tid & 7) << 2;    // 0,4..28
    const int r0  = tid >> 3;          // row-pair base for tid<128 (bwd)
    const int r1  = r0 + 16;

    // ---- preload constants, noise diagonals, t=0 inputs, init state ----
    for (int idx = tid; idx < 8192; idx += NT) sAm[idx] = g_A[idx];
    for (int idx = tid; idx < 8192; idx += NT) sBm[idx] = g_B[idx];
    for (int idx = tid; idx < 4096; idx += NT) sCm[idx] = g_C[idx];
    if (tid < 32) qd[tid] = expf(g_lQ[tid]);
    if (tid < 16) rd[tid] = expf(g_lR[tid]);
    {
        const size_t ib0 = (size_t)b * TLEN;
        if (tid < 8)  alB[tid] = g_alpha[ib0 * 8  + tid];
        if (tid < 32) suB[tid] = g_u    [ib0 * 32 + tid];
        if (tid < 16) saB[tid] = g_a    [ib0 * 16 + tid];
        if (tid < 32) { zm[tid] = g_z0m[tid]; zm2[tid] = g_z0m[tid]; }
        if (tid < 256) {
            float4 v = make_float4(0.f, 0.f, 0.f, 0.f);
            int d = i4 - j4;
            if (d >= 0 && d < 4) ((float*)&v)[d] = expf(g_z0lv[i4]);
            *(float4*)(pPp + i4 * LD + j4) = v;   // Ppred at t=0 = prior cov
        }
    }
    __syncthreads();

    // ---- preamble: mixtures for t=0 ----
    if (tid < 256) {
        float4 aa = make_float4(0.f,0.f,0.f,0.f);
        float4 bb = make_float4(0.f,0.f,0.f,0.f);
        #pragma unroll
        for (int k = 0; k < 8; ++k) {
            const float w = alB[k];
            float4 m = *(const float4*)(sAm + k * 1024 + i4 * 32 + j4);
            FMA4S(aa, w, m);
            m = *(const float4*)(sBm + k * 1024 + i4 * 32 + j4);
            FMA4S(bb, w, m);
        }
        *(float4*)(pA + i4 * LD + j4) = aa;
        pAtr[(j4+0)*LD + i4] = aa.x; pAtr[(j4+1)*LD + i4] = aa.y;
        pAtr[(j4+2)*LD + i4] = aa.z; pAtr[(j4+3)*LD + i4] = aa.w;
        *(float4*)(tmpM + i4 * LD + j4) = bb;
    } else if (tid < 384) {
        const int idx = tid - 256;
        const int ci = idx >> 3, cj = (idx & 7) << 2;
        float4 cc = make_float4(0.f,0.f,0.f,0.f);
        #pragma unroll
        for (int k = 0; k < 8; ++k) {
            const float w = alB[k];
            float4 m = *(const float4*)(sCm + k * 512 + ci * 32 + cj);
            FMA4S(cc, w, m);
        }
        *(float4*)(pCm + ci * LD + cj) = cc;
        pCtr[(cj+0)*LDCT + ci] = cc.x; pCtr[(cj+1)*LDCT + ci] = cc.y;
        pCtr[(cj+2)*LDCT + ci] = cc.z; pCtr[(cj+3)*LDCT + ci] = cc.w;
    }
    __syncthreads();

    // =============== FORWARD FILTER (also produces Y, N, zpred) ===============
    #pragma unroll 1
    for (int t = 0; t < TLEN; ++t) {
        const size_t ib = (size_t)b * TLEN + t;
        const int pb = t & 1, nb = pb ^ 1;
        const bool hasnext = (t + 1 < TLEN);

        // prefetch next step's inputs (side B high threads; stored at B0)
        float pfa = 0.f, pfu = 0.f, pfo = 0.f;
        if (hasnext && tid >= 448) {
            if (tid < 456)      pfa = g_alpha[(ib + 1) * 8  + (tid - 448)];
            else if (tid < 472) pfo = g_a    [(ib + 1) * 16 + (tid - 456)];
            else if (tid < 504) pfu = g_u    [(ib + 1) * 32 + (tid - 472)];
        }

        // ---- F1: N (side A) || CA, CQC, zm2+STG zpred (side B) ----
        if (t > 0) {
            if (tid < 256) {
                float4 n = mm4(pA + i4 * LD, zc, LD, j4);
                *(float4*)(aug0 + i4 * LDA + 32 + j4) = n;
                *(float4*)(g_Nm + (ib-1)*1024 + i4 * 32 + j4) = n;
            } else if (tid < 384) {
                const int idx = tid - 256;
                const int ci = idx >> 3, cj = (idx & 7) << 2;
                float4 ca = mm4(pCm + ci*LD, pA, LD, cj);
                CAtr[(cj+0)*LDCT + ci] = ca.x; CAtr[(cj+1)*LDCT + ci] = ca.y;
                CAtr[(cj+2)*LDCT + ci] = ca.z; CAtr[(cj+3)*LDCT + ci] = ca.w;
            } else if (tid < 448) {
                const int idx = tid - 384;
                const int qi = idx >> 2, qj = (idx & 3) << 2;
                float4 acc = make_float4(0.f,0.f,0.f,0.f);
                #pragma unroll
                for (int k0 = 0; k0 < 32; k0 += 4) {
                    float4 c4 = *(const float4*)(pCm + qi*LD + k0);
                    float4 q4 = *(const float4*)(qd + k0);
                    float4 bq;
                    bq = *(const float4*)(pCtr + (k0+0)*LDCT + qj); FMA4S(acc, c4.x*q4.x, bq);
                    bq = *(const float4*)(pCtr + (k0+1)*LDCT + qj); FMA4S(acc, c4.y*q4.y, bq);
                    bq = *(const float4*)(pCtr + (k0+2)*LDCT + qj); FMA4S(acc, c4.z*q4.z, bq);
                    bq = *(const float4*)(pCtr + (k0+3)*LDCT + qj); FMA4S(acc, c4.w*q4.w, bq);
                }
                *(float4*)(CQC + qi*LDCT + qj) = acc;
            } else if (tid >= 480) {
                const int i = tid - 480;
                const float* su = suB + pb * 32;
                float4 s4 = make_float4(0.f,0.f,0.f,0.f);
                #pragma unroll
                for (int k0 = 0; k0 < 32; k0 += 4) {
                    float4 m4 = *(const float4*)(tmpM + i * LD + k0);
                    float4 v4 = *(const float4*)(su + k0);
                    FMA4L(s4, m4, v4);
                    m4 = *(const float4*)(pA + i * LD + k0);
                    v4 = *(const float4*)(zm + k0);
                    FMA4L(s4, m4, v4);
                }
                float zp = (s4.x + s4.y) + (s4.z + s4.w);
                zm2[i] = zp;
                g_zp[(ib - 1) * 32 + i] = zp;
            }
        }
        __syncthreads();

        // ---- F2: Ppred (side A) || CN (side B) ; t==0: M = C·P0 ; apred ----
        if (t > 0) {
            if (tid < 256) {
                float4 p = mm4(aug0 + i4 * LDA + 32, pAtr, LD, j4);
                int d = i4 - j4;
                if (d >= 0 && d < 4) ((float*)&p)[d] += qd[i4];
                *(float4*)(pPp + i4 * LD + j4) = p;
                *(float4*)(aug0 + i4 * LDA + j4) = p;
            } else if (tid < 384) {
                const int idx = tid - 256;
                const int ci = idx >> 3, cj = (idx & 7) << 2;
                float4 cn = mm4(pCm + ci*LD, aug0 + 32, LDA, cj);
                *(float4*)(tmpM + ci*LD + cj) = cn;
            }
        } else {
            if (tid >= 256 && tid < 384) {
                const int idx = tid - 256;
                const int ci = idx >> 3, cj = (idx & 7) << 2;
                float4 m = mm4(pCm + ci*LD, pPp, LD, cj);
                *(float4*)(pCPm + ci*LD + cj) = m;
                *(float4*)(augS0 + ci*LDS2 + 16 + cj) = m;
            }
        }
        if (tid >= 448 && tid < 464) {
            const int i = tid - 448;
            float4 s4 = make_float4(0.f,0.f,0.f,0.f);
            #pragma unroll
            for (int k0 = 0; k0 < 32; k0 += 4) {
                float4 m4 = *(const float4*)(pCm + i * LD + k0);
                float4 v4 = *(const float4*)(zm2 + k0);
                FMA4L(s4, m4, v4);
            }
            apred[i] = (s4.x + s4.y) + (s4.z + s4.w);
        }
        __syncthreads();

        // ======== decoupled section ========
        if (tid < 256) {
            // ---- side A: Y-solve, 8 GJ phases, own barrier ----
            float* Ys = aug0; float* Yd = aug1;
            const int yi  = tid >> 3;
            const int yjA = (tid & 7) << 2;
            const int yjB = yjA + 32;
            #pragma unroll
            for (int pp = 0; pp < 8; ++pp) {
                if (t > 0) {
                    GJ4 s = gj4_pre(Ys, yi, pp << 2, LDA);
                    float4 EB = gj4_col4(s, Ys, yjB, LDA);
                    if (pp < 7) {
                        float4 EA = gj4_col4(s, Ys, yjA, LDA);
                        *(float4*)(Yd + yi * LDA + yjA) = EA;
                        *(float4*)(Yd + yi * LDA + yjB) = EB;
                    } else {
                        *(float4*)(g_Y + (ib-1)*1024 + yi*32 + (yjB-32)) = EB;
                    }
                }
                { float* w = Ys; Ys = Yd; Yd = w; }
                if (pp < 7) BAR_A();
            }
        } else {
            const int idx = tid - 256;
            // ---- B0: S-build (M, S) + prefetch stores ----
            if (t > 0) {
                if (idx < 128) {
                    const int i = idx >> 3, jj = (idx & 7) << 2;
                    float4 m = mm4(tmpM + i*LD, pAtr, LD, jj);
                    float4 c4 = *(const float4*)(pCm + i*LD + jj);
                    float4 q4 = *(const float4*)(qd + jj);
                    m.x = fmaf(c4.x, q4.x, m.x); m.y = fmaf(c4.y, q4.y, m.y);
                    m.z = fmaf(c4.z, q4.z, m.z); m.w = fmaf(c4.w, q4.w, m.w);
                    *(float4*)(pCPm + i*LD + jj) = m;
                    *(float4*)(augS0 + i*LDS2 + 16 + jj) = m;
                } else if (idx < 192) {
                    const int k = idx - 128;
                    const int i = k >> 2, jj = (k & 3) << 2;
                    float4 s = mm4(tmpM + i*LD, CAtr, LDCT, jj);
                    float4 cq = *(const float4*)(CQC + i*LDCT + jj);
                    s.x += cq.x; s.y += cq.y; s.z += cq.z; s.w += cq.w;
                    int d = i - jj;
                    if (d >= 0 && d < 4) ((float*)&s)[d] += rd[i];
                    *(float4*)(augS0 + i*LDS2 + jj) = s;
                }
            } else {
                if (idx >= 128 && idx < 192) {
                    const int k = idx - 128;
                    const int i = k >> 2, jj = (k & 3) << 2;
                    float4 s = mm4(pCPm + i*LD, pCtr, LDCT, jj);
                    int d = i - jj;
                    if (d >= 0 && d < 4) ((float*)&s)[d] += rd[i];
                    *(float4*)(augS0 + i*LDS2 + jj) = s;
                }
            }
            if (hasnext && tid >= 448) {
                if (tid < 456)      alB[nb*8  + (tid-448)] = pfa;
                else if (tid < 472) saB[nb*16 + (tid-456)] = pfo;
                else if (tid < 504) suB[nb*32 + (tid-472)] = pfu;
            }
            BAR_B();

            // ---- B1..B4: S-solve (4 pivot phases) + dz ----
            #pragma unroll
            for (int sp = 0; sp < 4; ++sp) {
                if (idx < 192) {
                    const int si = idx & 15;
                    const int sj = (idx >> 4) << 2;
                    float* Ss = (sp & 1) ? augS1 : augS0;
                    float* Sd = (sp & 1) ? augS0 : augS1;
                    if (sp < 3 || sj >= 16) {
                        GJ4 s = gj4_pre(Ss, si, sp << 2, LDS2);
                        float4 E = gj4_col4(s, Ss, sj, LDS2);
                        if (sp < 3) {
                            *(float4*)(Sd + si * LDS2 + sj) = E;
                        } else {
                            KT2[(sj-16+0)*LDK + si] = E.x;
                            KT2[(sj-16+1)*LDK + si] = E.y;
                            KT2[(sj-16+2)*LDK + si] = E.z;
                            KT2[(sj-16+3)*LDK + si] = E.w;
                        }
                    }
                } else if (sp == 0 && idx >= 192 && idx < 208) {
                    const int j = idx - 192;
                    dz[j] = saB[pb * 16 + j] - apred[j];
                }
                BAR_B();
            }

            // ---- B5: measurement update + outputs + next-step mixtures ----
            {
                const size_t ob = ib * 2112;
                const int ri = idx >> 3, jj = (idx & 7) << 2;
                float4 acc = *(const float4*)(pPp + ri*LD + jj);
                #pragma unroll
                for (int rr = 0; rr < 16; rr += 4) {
                    float4 k4 = *(const float4*)(KT2 + ri*LDK + rr);
                    float4 m;
                    m = *(const float4*)(pCPm + (rr+0)*LD + jj); acc = f4fma(-k4.x, m, acc);
                    m = *(const float4*)(pCPm + (rr+1)*LD + jj); acc = f4fma(-k4.y, m, acc);
                    m = *(const float4*)(pCPm + (rr+2)*LD + jj); acc = f4fma(-k4.z, m, acc);
                    m = *(const float4*)(pCPm + (rr+3)*LD + jj); acc = f4fma(-k4.w, m, acc);
                }
                *(float4*)(zc + ri*LD + jj) = acc;
                *(float4*)(out + ob + 32 + ri*32 + jj) = acc;
                if (t == TLEN - 1) *(float4*)(out + ob + 1088 + ri*32 + jj) = acc;
                if (tid >= 480) {
                    const int i = tid - 480;
                    float4 s4 = make_float4(0.f,0.f,0.f,0.f);
                    #pragma unroll
                    for (int rr = 0; rr < 16; rr += 4) {
                        float4 k4 = *(const float4*)(KT2 + i * LDK + rr);
                        float4 d4 = *(const float4*)(dz + rr);
                        FMA4L(s4, k4, d4);
                    }
                    float nm = zm2[i] + (s4.x + s4.y) + (s4.z + s4.w);
                    zm[i] = nm;
                    out[ob + i] = nm;
                    if (t == TLEN - 1) out[ob + 1056 + i] = nm;
                }
                if (hasnext) {
                    const float* al = alB + nb * 8;
                    float4 aa = make_float4(0.f,0.f,0.f,0.f);
                    float4 bb = make_float4(0.f,0.f,0.f,0.f);
                    #pragma unroll
                    for (int k = 0; k < 8; ++k) {
                        const float w = al[k];
                        float4 m = *(const float4*)(sAm + k * 1024 + ri * 32 + jj);
                        FMA4S(aa, w, m);
                        m = *(const float4*)(sBm + k * 1024 + ri * 32 + jj);
                        FMA4S(bb, w, m);
                    }
                    *(float4*)(pA + ri * LD + jj) = aa;
                    pAtr[(jj+0)*LD + ri] = aa.x; pAtr[(jj+1)*LD + ri] = aa.y;
                    pAtr[(jj+2)*LD + ri] = aa.z; pAtr[(jj+3)*LD + ri] = aa.w;
                    *(float4*)(tmpM + ri * LD + jj) = bb;
                    if (idx < 128) {
                        const int ci = idx >> 3, cj = (idx & 7) << 2;
                        float4 cc = make_float4(0.f,0.f,0.f,0.f);
                        #pragma unroll
                        for (int k = 0; k < 8; ++k) {
                            const float w = al[k];
                            float4 m = *(const float4*)(sCm + k * 512 + ci * 32 + cj);
                            FMA4S(cc, w, m);
                        }
                        *(float4*)(pCm + ci * LD + cj) = cc;
                        pCtr[(cj+0)*LDCT + ci] = cc.x; pCtr[(cj+1)*LDCT + ci] = cc.y;
                        pCtr[(cj+2)*LDCT + ci] = cc.z; pCtr[(cj+3)*LDCT + ci] = cc.w;
                    }
                }
            }
        }
        __syncthreads();
    }

    // =============== BACKWARD RTS SMOOTHER (2 phases/step) ===============
    {   // preload slot TLEN-2 into parity 0
        const size_t slot0 = (size_t)b * TLEN + (TLEN - 2);
        if (tid < 256) {
            float4 y = *(const float4*)(g_Y  + slot0 * 1024 + i4 * 32 + j4);
            float4 n = *(const float4*)(g_Nm + slot0 * 1024 + i4 * 32 + j4);
            *(float4*)(Ybuf + i4 * LD + j4) = y;
            YtrB[(j4+0)*LD + i4] = y.x; YtrB[(j4+1)*LD + i4] = y.y;
            YtrB[(j4+2)*LD + i4] = y.z; YtrB[(j4+3)*LD + i4] = y.w;
            *(float4*)(NbS + i4 * LD + j4) = n;
            *(float4*)(fcS + i4 * LD + j4) =
                *(const float4*)(out + slot0 * 2112 + 32 + i4 * 32 + j4);
        }
        if (tid < 32) {
            zpS[tid] = g_zp[slot0 * 32 + tid];
            fmS[tid] = out[slot0 * 2112 + tid];
        }
    }
    __syncthreads();

    #pragma unroll 1
    for (int t = TLEN - 2; t >= 0; --t) {
        const size_t ib = (size_t)b * TLEN + t;
        const size_t ob = ib * 2112;
        const int pb = t & 1;
        const int nb = pb ^ 1;
        const bool hasprev = (t > 0);

        float4 pfY = make_float4(0.f,0.f,0.f,0.f);
        float4 pfN = make_float4(0.f,0.f,0.f,0.f);
        float4 pfc = make_float4(0.f,0.f,0.f,0.f);
        float pfz = 0.f, pfm = 0.f;
        int pi = 0, pj = 0;
        if (tid >= 256) { const int idx = tid - 256; pi = idx >> 3; pj = (idx & 7) << 2; }
        if (hasprev) {
            const size_t sp = ib - 1;
            if (tid >= 256) {
                pfY = *(const float4*)(g_Y  + sp * 1024 + pi * 32 + pj);
                pfN = *(const float4*)(g_Nm + sp * 1024 + pi * 32 + pj);
                pfc = *(const float4*)(out + sp * 2112 + 32 + pi * 32 + pj);
            }
            if (tid >= 448 && tid < 480) {
                pfz = g_zp[sp * 32 + (tid - 448)];
                pfm = out[sp * 2112 + (tid - 448)];
            }
        }

        // ---- PW: W = Ps·Y - N (128 thr) ; zs2 (warp 15) ----
        if (tid < 128) {
            float4 o0, o1;
            mm24(zc + r0*LD, zc + r1*LD, Ybuf + pb*1152, LD, j4, o0, o1);
            float4 n0 = *(const float4*)(NbS + pb*1152 + r0*LD + j4);
            float4 n1 = *(const float4*)(NbS + pb*1152 + r1*LD + j4);
            o0.x -= n0.x; o0.y -= n0.y; o0.z -= n0.z; o0.w -= n0.w;
            o1.x -= n1.x; o1.y -= n1.y; o1.z -= n1.z; o1.w -= n1.w;
            *(float4*)(aug1 + r0*LDA + j4) = o0;
            *(float4*)(aug1 + r1*LDA + j4) = o1;
        } else if (tid >= 480) {
            const int i = tid - 480;
            float4 s4 = make_float4(0.f,0.f,0.f,0.f);
            #pragma unroll
            for (int k0 = 0; k0 < 32; k0 += 4) {
                float4 y4 = *(const float4*)(YtrB + pb*1152 + i*LD + k0);
                float4 z4 = *(const float4*)(zm + k0);
                float4 p4 = *(const float4*)(zpS + pb*32 + k0);
                float4 d4 = make_float4(z4.x-p4.x, z4.y-p4.y, z4.z-p4.z, z4.w-p4.w);
                FMA4L(s4, y4, d4);
            }
            zm2[i] = fmS[pb*32 + i] + (s4.x + s4.y) + (s4.z + s4.w);
        }
        __syncthreads();

        // ---- P21: Ps = fc + Ytr·W ; outputs ; store prefetch [nb] ----
        if (tid < 128) {
            float4 w0, w1;
            mm24(YtrB + pb*1152 + r0*LD, YtrB + pb*1152 + r1*LD, aug1, LDA, j4, w0, w1);
            float4 f0 = *(const float4*)(fcS + pb*1152 + r0*LD + j4);
            float4 f1 = *(const float4*)(fcS + pb*1152 + r1*LD + j4);
            f0.x += w0.x; f0.y += w0.y; f0.z += w0.z; f0.w += w0.w;
            f1.x += w1.x; f1.y += w1.y; f1.z += w1.z; f1.w += w1.w;
            *(float4*)(zc + r0*LD + j4) = f0;
            *(float4*)(zc + r1*LD + j4) = f1;
            *(float4*)(out + ob + 1088 + r0*32 + j4) = f0;
            *(float4*)(out + ob + 1088 + r1*32 + j4) = f1;
        }
        if (tid >= 256 && hasprev) {
            *(float4*)(Ybuf + nb*1152 + pi*LD + pj) = pfY;
            YtrB[nb*1152 + (pj+0)*LD + pi] = pfY.x;
            YtrB[nb*1152 + (pj+1)*LD + pi] = pfY.y;
            YtrB[nb*1152 + (pj+2)*LD + pi] = pfY.z;
            YtrB[nb*1152 + (pj+3)*LD + pi] = pfY.w;
            *(float4*)(NbS + nb*1152 + pi*LD + pj) = pfN;
            *(float4*)(fcS + nb*1152 + pi*LD + pj) = pfc;
        }
        if (tid >= 448 && tid < 480) {
            const int i = tid - 448;
            float nm = zm2[i];
            zm[i] = nm;
            out[ob + 1056 + i] = nm;
            if (hasprev) {
                zpS[nb*32 + i] = pfz;
                fmS[nb*32 + i] = pfm;
            }
        }
        __syncthreads();
    }
}

extern "C" void kernel_launch(void* const* d_in, const int* in_sizes, int n_in,
                              void* d_out, int out_size) {
    const float* g_a    = (const float*)d_in[0];
    const float* g_alpha= (const float*)d_in[1];
    const float* g_u    = (const float*)d_in[2];
    const float* g_A    = (const float*)d_in[3];
    const float* g_B    = (const float*)d_in[4];
    const float* g_C    = (const float*)d_in[5];
    const float* g_lQ   = (const float*)d_in[6];
    const float* g_lR   = (const float*)d_in[7];
    const float* g_z0m  = (const float*)d_in[8];
    const float* g_z0lv = (const float*)d_in[9];
    float* out = (float*)d_out;
    int B = in_sizes[0] / (TLEN * 16);
    size_t smem = SMEM_FLOATS * sizeof(float);
    cudaFuncSetAttribute(lgssm_kernel, cudaFuncAttributeMaxDynamicSharedMemorySize, (int)smem);
    lgssm_kernel<<<B, NT, smem>>>(g_a, g_alpha, g_u, g_A, g_B, g_C,
                                  g_lQ, g_lR, g_z0m, g_z0lv, out);
}

// round 13
// speedup vs baseline: 1.0398x; 1.0398x over previous
#include <cuda_runtime.h>

#define NT     512
#define TLEN   512
#define LD     36     // padded leading dim, 32-col matrices
#define LDA    68     // Y-augmented GJ matrix leading dim (32x64)
#define LDS2   52     // S-augmented GJ matrix leading dim (16x48)
#define LDCT   20     // C^T / CA^T / CQC leading dim
#define LDK    20     // KT2 leading dim
#define MAXB   128

// scratch produced by forward, consumed by ysolve/backward
__device__ float g_Y [MAXB * TLEN * 1024];
__device__ float g_Nm[MAXB * TLEN * 1024];
__device__ float g_Pp[MAXB * TLEN * 1024];
__device__ float g_zp[MAXB * TLEN * 32];

// ---- shared memory layout (float offsets) ----
#define O_SAM  0
#define O_SBM  8192
#define O_SCM  16384
#define O_A    20480   // 32xLD A_t
#define O_ATR  21632   // 32xLD A_t^T
#define O_CM   22784   // 16xLD C_t
#define O_CTR  23360   // 32xLDCT C_t^T
#define O_ZC   24000   // 32xLD covariance state
#define O_TMP  25152   // 32xLD B mixture
#define O_PP   26304   // 32xLD Ppred
#define O_CPM  27456   // 16xLD M
#define O_AUG0 28032   // 32xLDA N staging (fwd)
#define O_AUG1 30208   // fwd: CArm (576) + CNsh (@+1024, 576) ; bwd: W
#define O_AGS0 32384   // 16xLDS2 S-GJ buffer 0
#define O_AGS1 33216   // 16xLDS2 S-GJ buffer 1
#define O_KT2  34048   // 32xLDK Kg
#define O_FCS  34688   // 2 x 1152 filtered cov (parity)
#define O_FMS  36992   // 2 x 32
#define O_YB   37056   // 2 x 1152 Y (parity)
#define O_YT   39360   // 2 x 1152 Y^T (parity)
#define O_NB   41664   // 2 x 1152 N (parity)
#define O_ZPS  43968   // 2 x 32 zpred (parity)
#define O_ZM   44032
#define O_ZM2  44064
#define O_AL   44096   // 2 x 8
#define O_SU   44112   // 2 x 32
#define O_SA   44176   // 2 x 16
#define O_AP   44208   // 16
#define O_DZ   44224   // 32
#define O_QD   44256   // 32
#define O_RD   44288   // 16
#define O_CAT  44304   // 32xLDCT  CA^T
#define O_CQC  44944   // 16xLDCT  C diag(q) C^T
#define SMEM_FLOATS 45264

__device__ __forceinline__ float4 f4fma(float s, float4 b, float4 a) {
    return make_float4(fmaf(s,b.x,a.x), fmaf(s,b.y,a.y), fmaf(s,b.z,a.z), fmaf(s,b.w,a.w));
}
__device__ __forceinline__ float4 f4scale(float4 a, float s) {
    return make_float4(a.x*s, a.y*s, a.z*s, a.w*s);
}
#define FMA4S(acc, s, b)                                                      \
    acc.x = fmaf((s), (b).x, acc.x); acc.y = fmaf((s), (b).y, acc.y);         \
    acc.z = fmaf((s), (b).z, acc.z); acc.w = fmaf((s), (b).w, acc.w);
#define FMA4L(s4, m4, v4)                                                     \
    s4.x = fmaf(m4.x, v4.x, s4.x); s4.y = fmaf(m4.y, v4.y, s4.y);             \
    s4.z = fmaf(m4.z, v4.z, s4.z); s4.w = fmaf(m4.w, v4.w, s4.w);

__device__ __forceinline__ float4 mm4(const float* __restrict__ rowA,
                                      const float* __restrict__ matB,
                                      const int ldB, const int jj) {
    float4 a0 = make_float4(0.f,0.f,0.f,0.f);
    float4 a1 = make_float4(0.f,0.f,0.f,0.f);
    #pragma unroll
    for (int k0 = 0; k0 < 32; k0 += 8) {
        float4 x = *(const float4*)(rowA + k0);
        float4 y = *(const float4*)(rowA + k0 + 4);
        const float* Bp = matB + k0 * ldB + jj;
        float4 b;
        b = *(const float4*)(Bp);           FMA4S(a0, x.x, b);
        b = *(const float4*)(Bp + ldB);     FMA4S(a1, x.y, b);
        b = *(const float4*)(Bp + 2*ldB);   FMA4S(a0, x.z, b);
        b = *(const float4*)(Bp + 3*ldB);   FMA4S(a1, x.w, b);
        b = *(const float4*)(Bp + 4*ldB);   FMA4S(a0, y.x, b);
        b = *(const float4*)(Bp + 5*ldB);   FMA4S(a1, y.y, b);
        b = *(const float4*)(Bp + 6*ldB);   FMA4S(a0, y.z, b);
        b = *(const float4*)(Bp + 7*ldB);   FMA4S(a1, y.w, b);
    }
    return make_float4(a0.x + a1.x, a0.y + a1.y, a0.z + a1.z, a0.w + a1.w);
}

__device__ __forceinline__ void mm24(const float* __restrict__ rA0,
                                     const float* __restrict__ rA1,
                                     const float* __restrict__ matB,
                                     const int ldB, const int jj,
                                     float4& o0, float4& o1) {
    float4 a0 = make_float4(0.f,0.f,0.f,0.f);
    float4 a1 = make_float4(0.f,0.f,0.f,0.f);
    float4 c0 = make_float4(0.f,0.f,0.f,0.f);
    float4 c1 = make_float4(0.f,0.f,0.f,0.f);
    #pragma unroll
    for (int k0 = 0; k0 < 32; k0 += 4) {
        float4 x = *(const float4*)(rA0 + k0);
        float4 y = *(const float4*)(rA1 + k0);
        const float* Bp = matB + k0 * ldB + jj;
        float4 b;
        b = *(const float4*)(Bp);         FMA4S(a0, x.x, b); FMA4S(c0, y.x, b);
        b = *(const float4*)(Bp + ldB);   FMA4S(a1, x.y, b); FMA4S(c1, y.y, b);
        b = *(const float4*)(Bp + 2*ldB); FMA4S(a0, x.z, b); FMA4S(c0, y.z, b);
        b = *(const float4*)(Bp + 3*ldB); FMA4S(a1, x.w, b); FMA4S(c1, y.w, b);
    }
    o0 = make_float4(a0.x+a1.x, a0.y+a1.y, a0.z+a1.z, a0.w+a1.w);
    o1 = make_float4(c0.x+c1.x, c0.y+c1.y, c0.z+c1.z, c0.w+c1.w);
}

// ---- 4-pivot Gauss-Jordan block state ----
struct GJ4 {
    float inv0, inv1, inv2, inv3;
    float P10, P20, P30, a21, a31, a32;
    float c0, c1, c2, c3;
    int p0, gi;
};
__device__ __forceinline__ GJ4 gj4_pre(const float* __restrict__ Asrc, int gi,
                                       int p0, int lda) {
    GJ4 s; s.p0 = p0; s.gi = gi;
    const float4 R0 = *(const float4*)(Asrc + (p0+0)*lda + p0);
    const float4 R1 = *(const float4*)(Asrc + (p0+1)*lda + p0);
    const float4 R2 = *(const float4*)(Asrc + (p0+2)*lda + p0);
    const float4 R3 = *(const float4*)(Asrc + (p0+3)*lda + p0);
    const float4 Ci = *(const float4*)(Asrc + gi*lda + p0);
    s.inv0 = __fdividef(1.f, R0.x);
    float u01 = R0.y*s.inv0, u02 = R0.z*s.inv0, u03 = R0.w*s.inv0;
    s.P10 = R1.x;
    float a11 = fmaf(-R1.x, u01, R1.y);  s.inv1 = __fdividef(1.f, a11);
    float a12 = fmaf(-R1.x, u02, R1.z), a13 = fmaf(-R1.x, u03, R1.w);
    float v12 = a12*s.inv1, v13 = a13*s.inv1;
    s.P20 = R2.x;
    s.a21 = fmaf(-R2.x, u01, R2.y);
    float a22 = fmaf(-s.a21, v12, fmaf(-R2.x, u02, R2.z));
    s.inv2 = __fdividef(1.f, a22);
    float a23 = fmaf(-s.a21, v13, fmaf(-R2.x, u03, R2.w));
    float w23 = a23*s.inv2;
    s.P30 = R3.x;
    s.a31 = fmaf(-R3.x, u01, R3.y);
    s.a32 = fmaf(-s.a31, v12, fmaf(-R3.x, u02, R3.z));
    float a33 = fmaf(-s.a32, w23, fmaf(-s.a31, v13, fmaf(-R3.x, u03, R3.w)));
    s.inv3 = __fdividef(1.f, a33);
    s.c0 = Ci.x;
    s.c1 = (gi==p0)   ? u01 : fmaf(-s.c0, u01, Ci.y);
    float c2t = (gi==p0)   ? u02 : fmaf(-s.c0, u02, Ci.z);
    s.c2 = (gi==p0+1) ? v12 : fmaf(-s.c1, v12, c2t);
    float c3t = (gi==p0)   ? u03 : fmaf(-s.c0, u03, Ci.w);
    float c3u = (gi==p0+1) ? v13 : fmaf(-s.c1, v13, c3t);
    s.c3 = (gi==p0+2) ? w23 : fmaf(-s.c2, w23, c3u);
    return s;
}
__device__ __forceinline__ float4 gj4_col4(const GJ4& s, const float* __restrict__ Asrc,
                                           int jj, int lda) {
    const int p0 = s.p0, gi = s.gi;
    float4 m0 = *(const float4*)(Asrc + (p0+0)*lda + jj);
    float4 m1 = *(const float4*)(Asrc + (p0+1)*lda + jj);
    float4 m2 = *(const float4*)(Asrc + (p0+2)*lda + jj);
    float4 m3 = *(const float4*)(Asrc + (p0+3)*lda + jj);
    float4 mi = *(const float4*)(Asrc + gi*lda + jj);
    float4 r0 = f4scale(m0, s.inv0);
    float4 E  = (gi==p0)   ? r0 : f4fma(-s.c0, r0, mi);
    float4 t1 = f4fma(-s.P10, r0, m1);
    float4 r1 = f4scale(t1, s.inv1);
    E = (gi==p0+1) ? r1 : f4fma(-s.c1, r1, E);
    float4 t2 = f4fma(-s.a21, r1, f4fma(-s.P20, r0, m2));
    float4 r2 = f4scale(t2, s.inv2);
    E = (gi==p0+2) ? r2 : f4fma(-s.c2, r2, E);
    float4 t3 = f4fma(-s.a32, r2, f4fma(-s.a31, r1, f4fma(-s.P30, r0, m3)));
    float4 r3 = f4scale(t3, s.inv3);
    E = (gi==p0+3) ? r3 : f4fma(-s.c3, r3, E);
    return E;
}

// ===================== K1: forward filter =====================
__global__ __launch_bounds__(NT, 1)
void lgssm_fwd(const float* __restrict__ g_a,   const float* __restrict__ g_alpha,
               const float* __restrict__ g_u,   const float* __restrict__ g_A,
               const float* __restrict__ g_B,   const float* __restrict__ g_C,
               const float* __restrict__ g_lQ,  const float* __restrict__ g_lR,
               const float* __restrict__ g_z0m, const float* __restrict__ g_z0lv,
               float* __restrict__ out)
{
    extern __shared__ float sh[];
    float* sAm  = sh + O_SAM;
    float* sBm  = sh + O_SBM;
    float* sCm  = sh + O_SCM;
    float* pA   = sh + O_A;
    float* pAtr = sh + O_ATR;
    float* pCm  = sh + O_CM;
    float* pCtr = sh + O_CTR;
    float* zc   = sh + O_ZC;
    float* tmpM = sh + O_TMP;
    float* pPp  = sh + O_PP;
    float* pCPm = sh + O_CPM;
    float* aug0 = sh + O_AUG0;
    float* CArm = sh + O_AUG1;          // 16xLD
    float* CNsh = sh + O_AUG1 + 1024;   // 16xLD
    float* augS0= sh + O_AGS0;
    float* augS1= sh + O_AGS1;
    float* KT2  = sh + O_KT2;
    float* zm   = sh + O_ZM;
    float* zm2  = sh + O_ZM2;
    float* alB  = sh + O_AL;
    float* suB  = sh + O_SU;
    float* saB  = sh + O_SA;
    float* apred= sh + O_AP;
    float* dz   = sh + O_DZ;
    float* qd   = sh + O_QD;
    float* rd   = sh + O_RD;
    float* CAtr = sh + O_CAT;
    float* CQC  = sh + O_CQC;

    const int tid = threadIdx.x;
    const int b   = blockIdx.x;
    const int i4  = tid >> 3;          // 0..31 for tid<256
    const int j4  = (tid & 7) << 2;

    for (int idx = tid; idx < 8192; idx += NT) sAm[idx] = g_A[idx];
    for (int idx = tid; idx < 8192; idx += NT) sBm[idx] = g_B[idx];
    for (int idx = tid; idx < 4096; idx += NT) sCm[idx] = g_C[idx];
    if (tid < 32) qd[tid] = expf(g_lQ[tid]);
    if (tid < 16) rd[tid] = expf(g_lR[tid]);
    {
        const size_t ib0 = (size_t)b * TLEN;
        if (tid < 8)  alB[tid] = g_alpha[ib0 * 8  + tid];
        if (tid < 32) suB[tid] = g_u    [ib0 * 32 + tid];
        if (tid < 16) saB[tid] = g_a    [ib0 * 16 + tid];
        if (tid < 32) { zm[tid] = g_z0m[tid]; zm2[tid] = g_z0m[tid]; }
        if (tid < 256) {
            float4 v = make_float4(0.f, 0.f, 0.f, 0.f);
            int d = i4 - j4;
            if (d >= 0 && d < 4) ((float*)&v)[d] = expf(g_z0lv[i4]);
            *(float4*)(pPp + i4 * LD + j4) = v;   // Ppred at t=0 = prior cov
        }
    }
    __syncthreads();

    // prolog: mixtures for t=0 (A,B on [0,256); C on [256,384))
    if (tid < 256) {
        float4 aa = make_float4(0.f,0.f,0.f,0.f);
        float4 bb = make_float4(0.f,0.f,0.f,0.f);
        #pragma unroll
        for (int k = 0; k < 8; ++k) {
            const float w = alB[k];
            float4 m = *(const float4*)(sAm + k * 1024 + i4 * 32 + j4);
            FMA4S(aa, w, m);
            m = *(const float4*)(sBm + k * 1024 + i4 * 32 + j4);
            FMA4S(bb, w, m);
        }
        *(float4*)(pA + i4 * LD + j4) = aa;
        pAtr[(j4+0)*LD + i4] = aa.x; pAtr[(j4+1)*LD + i4] = aa.y;
        pAtr[(j4+2)*LD + i4] = aa.z; pAtr[(j4+3)*LD + i4] = aa.w;
        *(float4*)(tmpM + i4 * LD + j4) = bb;
    } else if (tid < 384) {
        const int idx = tid - 256;
        const int ci = idx >> 3, cj = (idx & 7) << 2;
        float4 cc = make_float4(0.f,0.f,0.f,0.f);
        #pragma unroll
        for (int k = 0; k < 8; ++k) {
            const float w = alB[k];
            float4 m = *(const float4*)(sCm + k * 512 + ci * 32 + cj);
            FMA4S(cc, w, m);
        }
        *(float4*)(pCm + ci * LD + cj) = cc;
        pCtr[(cj+0)*LDCT + ci] = cc.x; pCtr[(cj+1)*LDCT + ci] = cc.y;
        pCtr[(cj+2)*LDCT + ci] = cc.z; pCtr[(cj+3)*LDCT + ci] = cc.w;
    }
    __syncthreads();

    #pragma unroll 1
    for (int t = 0; t < TLEN; ++t) {
        const size_t ib = (size_t)b * TLEN + t;
        const int pb = t & 1, nb = pb ^ 1;
        const bool hasnext = (t + 1 < TLEN);

        // prefetch next step's inputs (threads 448-503; stored at F2)
        float pfa = 0.f, pfu = 0.f, pfo = 0.f;
        if (hasnext && tid >= 448) {
            if (tid < 456)      pfa = g_alpha[(ib + 1) * 8  + (tid - 448)];
            else if (tid < 472) pfo = g_a    [(ib + 1) * 16 + (tid - 456)];
            else if (tid < 504) pfu = g_u    [(ib + 1) * 32 + (tid - 472)];
        }

        // ---- F1: N = A·zc (+STG) || CN = CA·zc || zpred (+STG) ----
        if (t > 0) {
            if (tid < 256) {
                float4 n = mm4(pA + i4 * LD, zc, LD, j4);
                *(float4*)(aug0 + i4 * LDA + 32 + j4) = n;
                *(float4*)(g_Nm + (ib-1)*1024 + i4 * 32 + j4) = n;
            } else if (tid < 384) {
                const int idx = tid - 256;
                const int ci = idx >> 3, cj = (idx & 7) << 2;
                float4 cn = mm4(CArm + ci*LD, zc, LD, cj);
                *(float4*)(CNsh + ci*LD + cj) = cn;
            } else if (tid >= 480) {
                const int i = tid - 480;
                const float* su = suB + pb * 32;
                float4 s4 = make_float4(0.f,0.f,0.f,0.f);
                #pragma unroll
                for (int k0 = 0; k0 < 32; k0 += 4) {
                    float4 m4 = *(const float4*)(tmpM + i * LD + k0);
                    float4 v4 = *(const float4*)(su + k0);
                    FMA4L(s4, m4, v4);
                    m4 = *(const float4*)(pA + i * LD + k0);
                    v4 = *(const float4*)(zm + k0);
                    FMA4L(s4, m4, v4);
                }
                float zp = (s4.x + s4.y) + (s4.z + s4.w);
                zm2[i] = zp;
                g_zp[(ib - 1) * 32 + i] = zp;
            }
        }
        __syncthreads();

        // ---- F2: Ppred (+STG) || M || S || apred || prefetch stores ----
        if (t > 0) {
            if (tid < 256) {
                float4 p = mm4(aug0 + i4 * LDA + 32, pAtr, LD, j4);
                int d = i4 - j4;
                if (d >= 0 && d < 4) ((float*)&p)[d] += qd[i4];
                *(float4*)(pPp + i4 * LD + j4) = p;
                *(float4*)(g_Pp + (ib-1)*1024 + i4 * 32 + j4) = p;
            } else if (tid < 384) {
                const int idx = tid - 256;
                const int ci = idx >> 3, cj = (idx & 7) << 2;
                float4 m = mm4(CNsh + ci*LD, pAtr, LD, cj);
                float4 c4 = *(const float4*)(pCm + ci*LD + cj);
                float4 q4 = *(const float4*)(qd + cj);
                m.x = fmaf(c4.x, q4.x, m.x); m.y = fmaf(c4.y, q4.y, m.y);
                m.z = fmaf(c4.z, q4.z, m.z); m.w = fmaf(c4.w, q4.w, m.w);
                *(float4*)(pCPm + ci*LD + cj) = m;
                *(float4*)(augS0 + ci*LDS2 + 16 + cj) = m;
            } else if (tid < 448) {
                const int idx = tid - 384;
                const int si = idx >> 2, sj = (idx & 3) << 2;
                float4 s = mm4(CNsh + si*LD, CAtr, LDCT, sj);
                float4 cq = *(const float4*)(CQC + si*LDCT + sj);
                s.x += cq.x; s.y += cq.y; s.z += cq.z; s.w += cq.w;
                int d = si - sj;
                if (d >= 0 && d < 4) ((float*)&s)[d] += rd[si];
                *(float4*)(augS0 + si*LDS2 + sj) = s;
            }
        } else {
            if (tid >= 256 && tid < 384) {
                const int idx = tid - 256;
                const int ci = idx >> 3, cj = (idx & 7) << 2;
                float4 m = mm4(pCm + ci*LD, pPp, LD, cj);
                *(float4*)(pCPm + ci*LD + cj) = m;
                *(float4*)(augS0 + ci*LDS2 + 16 + cj) = m;
            }
        }
        if (tid >= 448 && tid < 464) {
            const int i = tid - 448;
            float4 s4 = make_float4(0.f,0.f,0.f,0.f);
            #pragma unroll
            for (int k0 = 0; k0 < 32; k0 += 4) {
                float4 m4 = *(const float4*)(pCm + i * LD + k0);
                float4 v4 = *(const float4*)(zm2 + k0);
                FMA4L(s4, m4, v4);
            }
            apred[i] = (s4.x + s4.y) + (s4.z + s4.w);
        }
        if (hasnext && tid >= 448) {
            if (tid < 456)      alB[nb*8  + (tid-448)] = pfa;
            else if (tid < 472) saB[nb*16 + (tid-456)] = pfo;
            else if (tid < 504) suB[nb*32 + (tid-472)] = pfu;
        }
        __syncthreads();

        if (t == 0) {   // extra phase: build S from M (only once)
            if (tid < 64) {
                const int si = tid >> 2, sj = (tid & 3) << 2;
                float4 s = mm4(pCPm + si*LD, pCtr, LDCT, sj);
                int d = si - sj;
                if (d >= 0 && d < 4) ((float*)&s)[d] += rd[si];
                *(float4*)(augS0 + si*LDS2 + sj) = s;
            }
            __syncthreads();
        }

        // ---- S0..S3: S-solve (thr<192) + dz + next mixtures/CA/CQC ----
        #pragma unroll
        for (int sp = 0; sp < 4; ++sp) {
            if (tid < 192) {
                const int si = tid & 15;
                const int sj = (tid >> 4) << 2;
                float* Ss = (sp & 1) ? augS1 : augS0;
                float* Sd = (sp & 1) ? augS0 : augS1;
                if (sp < 3 || sj >= 16) {
                    GJ4 s = gj4_pre(Ss, si, sp << 2, LDS2);
                    float4 E = gj4_col4(s, Ss, sj, LDS2);
                    if (sp < 3) {
                        *(float4*)(Sd + si * LDS2 + sj) = E;
                    } else {
                        KT2[(sj-16+0)*LDK + si] = E.x;
                        KT2[(sj-16+1)*LDK + si] = E.y;
                        KT2[(sj-16+2)*LDK + si] = E.z;
                        KT2[(sj-16+3)*LDK + si] = E.w;
                    }
                }
            } else if (sp == 0) {
                if (tid < 208) {
                    const int j = tid - 192;
                    dz[j] = saB[pb * 16 + j] - apred[j];
                } else if (hasnext && tid < 464) {
                    const int cell = tid - 208;
                    const int ri = cell >> 3, jj = (cell & 7) << 2;
                    const float* al = alB + nb * 8;
                    float4 aa = make_float4(0.f,0.f,0.f,0.f);
                    float4 bb = make_float4(0.f,0.f,0.f,0.f);
                    #pragma unroll
                    for (int k = 0; k < 8; ++k) {
                        const float w = al[k];
                        float4 m = *(const float4*)(sAm + k * 1024 + ri * 32 + jj);
                        FMA4S(aa, w, m);
                        m = *(const float4*)(sBm + k * 1024 + ri * 32 + jj);
                        FMA4S(bb, w, m);
                    }
                    *(float4*)(pA + ri * LD + jj) = aa;
                    pAtr[(jj+0)*LD + ri] = aa.x; pAtr[(jj+1)*LD + ri] = aa.y;
                    pAtr[(jj+2)*LD + ri] = aa.z; pAtr[(jj+3)*LD + ri] = aa.w;
                    *(float4*)(tmpM + ri * LD + jj) = bb;
                }
            } else if (sp == 1) {
                if (hasnext && tid >= 208 && tid < 336) {
                    const int cell = tid - 208;
                    const int ci = cell >> 3, cj = (cell & 7) << 2;
                    const float* al = alB + nb * 8;
                    float4 cc = make_float4(0.f,0.f,0.f,0.f);
                    #pragma unroll
                    for (int k = 0; k < 8; ++k) {
                        const float w = al[k];
                        float4 m = *(const float4*)(sCm + k * 512 + ci * 32 + cj);
                        FMA4S(cc, w, m);
                    }
                    *(float4*)(pCm + ci * LD + cj) = cc;
                    pCtr[(cj+0)*LDCT + ci] = cc.x; pCtr[(cj+1)*LDCT + ci] = cc.y;
                    pCtr[(cj+2)*LDCT + ci] = cc.z; pCtr[(cj+3)*LDCT + ci] = cc.w;
                }
            } else if (sp == 2) {
                if (hasnext && tid >= 208 && tid < 336) {
                    const int cell = tid - 208;
                    const int ci = cell >> 3, cj = (cell & 7) << 2;
                    float4 ca = mm4(pCm + ci*LD, pA, LD, cj);
                    *(float4*)(CArm + ci*LD + cj) = ca;
                    CAtr[(cj+0)*LDCT + ci] = ca.x; CAtr[(cj+1)*LDCT + ci] = ca.y;
                    CAtr[(cj+2)*LDCT + ci] = ca.z; CAtr[(cj+3)*LDCT + ci] = ca.w;
                }
            } else {   // sp == 3
                if (hasnext && tid >= 208 && tid < 272) {
                    const int cell = tid - 208;
                    const int qi = cell >> 2, qj = (cell & 3) << 2;
                    float4 acc = make_float4(0.f,0.f,0.f,0.f);
                    #pragma unroll
                    for (int k0 = 0; k0 < 32; k0 += 4) {
                        float4 c4 = *(const float4*)(pCm + qi*LD + k0);
                        float4 q4 = *(const float4*)(qd + k0);
                        float4 bq;
                        bq = *(const float4*)(pCtr + (k0+0)*LDCT + qj); FMA4S(acc, c4.x*q4.x, bq);
                        bq = *(const float4*)(pCtr + (k0+1)*LDCT + qj); FMA4S(acc, c4.y*q4.y, bq);
                        bq = *(const float4*)(pCtr + (k0+2)*LDCT + qj); FMA4S(acc, c4.z*q4.z, bq);
                        bq = *(const float4*)(pCtr + (k0+3)*LDCT + qj); FMA4S(acc, c4.w*q4.w, bq);
                    }
                    *(float4*)(CQC + qi*LDCT + qj) = acc;
                }
            }
            __syncthreads();
        }

        // ---- F7: measurement update + filtered output ----
        {
            const size_t ob = ib * 2112;
            if (tid < 256) {
                float4 acc = *(const float4*)(pPp + i4*LD + j4);
                #pragma unroll
                for (int rr = 0; rr < 16; rr += 4) {
                    float4 k4 = *(const float4*)(KT2 + i4*LDK + rr);
                    float4 m;
                    m = *(const float4*)(pCPm + (rr+0)*LD + j4); acc = f4fma(-k4.x, m, acc);
                    m = *(const float4*)(pCPm + (rr+1)*LD + j4); acc = f4fma(-k4.y, m, acc);
                    m = *(const float4*)(pCPm + (rr+2)*LD + j4); acc = f4fma(-k4.z, m, acc);
                    m = *(const float4*)(pCPm + (rr+3)*LD + j4); acc = f4fma(-k4.w, m, acc);
                }
                *(float4*)(zc + i4*LD + j4) = acc;
                *(float4*)(out + ob + 32 + i4*32 + j4) = acc;
                if (t == TLEN - 1) *(float4*)(out + ob + 1088 + i4*32 + j4) = acc;
            } else if (tid >= 480) {
                const int i = tid - 480;
                float4 s4 = make_float4(0.f,0.f,0.f,0.f);
                #pragma unroll
                for (int rr = 0; rr < 16; rr += 4) {
                    float4 k4 = *(const float4*)(KT2 + i * LDK + rr);
                    float4 d4 = *(const float4*)(dz + rr);
                    FMA4L(s4, k4, d4);
                }
                float nm = zm2[i] + (s4.x + s4.y) + (s4.z + s4.w);
                zm[i] = nm;
                out[ob + i] = nm;
                if (t == TLEN - 1) out[ob + 1056 + i] = nm;
            }
        }
        __syncthreads();
    }
}

// ===================== K2: batched Y-solves =====================
// one warp per solve; warp-synchronous GJ with dead-column pruning
__global__ __launch_bounds__(64, 8)
void lgssm_ysolve(int nsolve)
{
    extern __shared__ float sm[];
    const int w    = threadIdx.x >> 5;
    const int lane = threadIdx.x & 31;
    const long long sid = (long long)blockIdx.x * 2 + w;
    if (sid >= nsolve) return;
    const int bb = (int)(sid / 511);
    const int ss = (int)(sid % 511);
    const size_t slot = (size_t)bb * TLEN + ss;

    float* A0 = sm + w * 4352;
    float* A1 = A0 + 2176;

    const float* Pp = g_Pp + slot * 1024 + lane * 32;
    const float* Nm = g_Nm + slot * 1024 + lane * 32;
    #pragma unroll
    for (int g = 0; g < 8; ++g) {
        *(float4*)(A0 + lane*LDA + (g<<2))      = *(const float4*)(Pp + (g<<2));
        *(float4*)(A0 + lane*LDA + 32 + (g<<2)) = *(const float4*)(Nm + (g<<2));
    }
    __syncwarp();

    float* Asrc = A0; float* Adst = A1;
    #pragma unroll 1
    for (int pp = 0; pp < 8; ++pp) {
        GJ4 s = gj4_pre(Asrc, lane, pp << 2, LDA);
        if (pp < 7) {
            #pragma unroll 1
            for (int g = pp + 1; g < 16; ++g) {
                const int jj = g << 2;
                float4 E = gj4_col4(s, Asrc, jj, LDA);
                *(float4*)(Adst + lane*LDA + jj) = E;
            }
        } else {
            #pragma unroll
            for (int g = 8; g < 16; ++g) {
                const int jj = g << 2;
                float4 E = gj4_col4(s, Asrc, jj, LDA);
                *(float4*)(g_Y + slot*1024 + lane*32 + (jj - 32)) = E;
            }
        }
        float* tt = Asrc; Asrc = Adst; Adst = tt;
        __syncwarp();
    }
}

// ===================== K3: backward smoother =====================
__global__ __launch_bounds__(NT, 1)
void lgssm_bwd(float* __restrict__ out)
{
    extern __shared__ float sh[];
    float* aug1 = sh + O_AUG1;
    float* fcS  = sh + O_FCS;
    float* fmS  = sh + O_FMS;
    float* Ybuf = sh + O_YB;
    float* YtrB = sh + O_YT;
    float* NbS  = sh + O_NB;
    float* zpS  = sh + O_ZPS;
    float* zm   = sh + O_ZM;
    float* zm2  = sh + O_ZM2;
    float* zc   = sh + O_ZC;

    const int tid = threadIdx.x;
    const int b   = blockIdx.x;
    const int i4  = tid >> 3;
    const int j4  = (tid & 7) << 2;
    const int r0  = tid >> 3;
    const int r1  = r0 + 16;

    {   // init state + preload slot TLEN-2 into parity 0
        const size_t obL   = ((size_t)b * TLEN + (TLEN - 1)) * 2112;
        const size_t slot0 = (size_t)b * TLEN + (TLEN - 2);
        if (tid < 32) zm[tid] = out[obL + tid];
        if (tid < 256) {
            *(float4*)(zc + i4 * LD + j4) =
                *(const float4*)(out + obL + 32 + i4 * 32 + j4);
            float4 y = *(const float4*)(g_Y  + slot0 * 1024 + i4 * 32 + j4);
            float4 n = *(const float4*)(g_Nm + slot0 * 1024 + i4 * 32 + j4);
            *(float4*)(Ybuf + i4 * LD + j4) = y;
            YtrB[(j4+0)*LD + i4] = y.x; YtrB[(j4+1)*LD + i4] = y.y;
            YtrB[(j4+2)*LD + i4] = y.z; YtrB[(j4+3)*LD + i4] = y.w;
            *(float4*)(NbS + i4 * LD + j4) = n;
            *(float4*)(fcS + i4 * LD + j4) =
                *(const float4*)(out + slot0 * 2112 + 32 + i4 * 32 + j4);
        }
        if (tid < 32) {
            zpS[tid] = g_zp[slot0 * 32 + tid];
            fmS[tid] = out[slot0 * 2112 + tid];
        }
    }
    __syncthreads();

    #pragma unroll 1
    for (int t = TLEN - 2; t >= 0; --t) {
        const size_t ib = (size_t)b * TLEN + t;
        const size_t ob = ib * 2112;
        const int pb = t & 1;
        const int nb = pb ^ 1;
        const bool hasprev = (t > 0);

        float4 pfY = make_float4(0.f,0.f,0.f,0.f);
        float4 pfN = make_float4(0.f,0.f,0.f,0.f);
        float4 pfc = make_float4(0.f,0.f,0.f,0.f);
        float pfz = 0.f, pfm = 0.f;
        int pi = 0, pj = 0;
        if (tid >= 256) { const int idx = tid - 256; pi = idx >> 3; pj = (idx & 7) << 2; }
        if (hasprev) {
            const size_t sp = ib - 1;
            if (tid >= 256) {
                pfY = *(const float4*)(g_Y  + sp * 1024 + pi * 32 + pj);
                pfN = *(const float4*)(g_Nm + sp * 1024 + pi * 32 + pj);
                pfc = *(const float4*)(out + sp * 2112 + 32 + pi * 32 + pj);
            }
            if (tid >= 448 && tid < 480) {
                pfz = g_zp[sp * 32 + (tid - 448)];
                pfm = out[sp * 2112 + (tid - 448)];
            }
        }

        // ---- PW: W = Ps·Y - N (128 thr) ; zs2 (warp 15) ----
        if (tid < 128) {
            float4 o0, o1;
            mm24(zc + r0*LD, zc + r1*LD, Ybuf + pb*1152, LD, j4, o0, o1);
            float4 n0 = *(const float4*)(NbS + pb*1152 + r0*LD + j4);
            float4 n1 = *(const float4*)(NbS + pb*1152 + r1*LD + j4);
            o0.x -= n0.x; o0.y -= n0.y; o0.z -= n0.z; o0.w -= n0.w;
            o1.x -= n1.x; o1.y -= n1.y; o1.z -= n1.z; o1.w -= n1.w;
            *(float4*)(aug1 + r0*LDA + j4) = o0;
            *(float4*)(aug1 + r1*LDA + j4) = o1;
        } else if (tid >= 480) {
            const int i = tid - 480;
            float4 s4 = make_float4(0.f,0.f,0.f,0.f);
            #pragma unroll
            for (int k0 = 0; k0 < 32; k0 += 4) {
                float4 y4 = *(const float4*)(YtrB + pb*1152 + i*LD + k0);
                float4 z4 = *(const float4*)(zm + k0);
                float4 p4 = *(const float4*)(zpS + pb*32 + k0);
                float4 d4 = make_float4(z4.x-p4.x, z4.y-p4.y, z4.z-p4.z, z4.w-p4.w);
                FMA4L(s4, y4, d4);
            }
            zm2[i] = fmS[pb*32 + i] + (s4.x + s4.y) + (s4.z + s4.w);
        }
        __syncthreads();

        // ---- P21: Ps = fc + Ytr·W ; outputs ; store prefetch [nb] ----
        if (tid < 128) {
            float4 w0, w1;
            mm24(YtrB + pb*1152 + r0*LD, YtrB + pb*1152 + r1*LD, aug1, LDA, j4, w0, w1);
            float4 f0 = *(const float4*)(fcS + pb*1152 + r0*LD + j4);
            float4 f1 = *(const float4*)(fcS + pb*1152 + r1*LD + j4);
            f0.x += w0.x; f0.y += w0.y; f0.z += w0.z; f0.w += w0.w;
            f1.x += w1.x; f1.y += w1.y; f1.z += w1.z; f1.w += w1.w;
            *(float4*)(zc + r0*LD + j4) = f0;
            *(float4*)(zc + r1*LD + j4) = f1;
            *(float4*)(out + ob + 1088 + r0*32 + j4) = f0;
            *(float4*)(out + ob + 1088 + r1*32 + j4) = f1;
        }
        if (tid >= 256 && hasprev) {
            *(float4*)(Ybuf + nb*1152 + pi*LD + pj) = pfY;
            YtrB[nb*1152 + (pj+0)*LD + pi] = pfY.x;
            YtrB[nb*1152 + (pj+1)*LD + pi] = pfY.y;
            YtrB[nb*1152 + (pj+2)*LD + pi] = pfY.z;
            YtrB[nb*1152 + (pj+3)*LD + pi] = pfY.w;
            *(float4*)(NbS + nb*1152 + pi*LD + pj) = pfN;
            *(float4*)(fcS + nb*1152 + pi*LD + pj) = pfc;
        }
        if (tid >= 448 && tid < 480) {
            const int i = tid - 448;
            float nm = zm2[i];
            zm[i] = nm;
            out[ob + 1056 + i] = nm;
            if (hasprev) {
                zpS[nb*32 + i] = pfz;
                fmS[nb*32 + i] = pfm;
            }
        }
        __syncthreads();
    }
}

extern "C" void kernel_launch(void* const* d_in, const int* in_sizes, int n_in,
                              void* d_out, int out_size) {
    const float* g_a    = (const float*)d_in[0];
    const float* g_alpha= (const float*)d_in[1];
    const float* g_u    = (const float*)d_in[2];
    const float* g_Ai   = (const float*)d_in[3];
    const float* g_Bi   = (const float*)d_in[4];
    const float* g_Ci   = (const float*)d_in[5];
    const float* g_lQ   = (const float*)d_in[6];
    const float* g_lR   = (const float*)d_in[7];
    const float* g_z0m  = (const float*)d_in[8];
    const float* g_z0lv = (const float*)d_in[9];
    float* out = (float*)d_out;
    int B = in_sizes[0] / (TLEN * 16);
    size_t smem = SMEM_FLOATS * sizeof(float);
    cudaFuncSetAttribute(lgssm_fwd, cudaFuncAttributeMaxDynamicSharedMemorySize, (int)smem);
    cudaFuncSetAttribute(lgssm_bwd, cudaFuncAttributeMaxDynamicSharedMemorySize, (int)smem);
    cudaFuncSetAttribute(lgssm_ysolve, cudaFuncAttributeMaxDynamicSharedMemorySize, 34816);
    lgssm_fwd<<<B, NT, smem>>>(g_a, g_alpha, g_u, g_Ai, g_Bi, g_Ci,
                               g_lQ, g_lR, g_z0m, g_z0lv, out);
    int nsolve = B * (TLEN - 1);
    int grid2 = (nsolve + 1) / 2;
    lgssm_ysolve<<<grid2, 64, 34816>>>(nsolve);
    lgssm_bwd<<<B, NT, smem>>>(out);
}

// round 14
// speedup vs baseline: 1.1399x; 1.0963x over previous
#include <cuda_runtime.h>

#define NT     512
#define TLEN   512
#define LD     36     // padded leading dim, 32-col matrices
#define LDA    68     // Y-augmented GJ matrix leading dim (32x64)
#define LDS2   52     // S-augmented GJ matrix leading dim (16x48)
#define LDCT   20     // C^T / CA^T / CQC leading dim
#define LDK    20     // KT2 leading dim
#define MAXB   128

// scratch produced by forward, consumed by ysolve/backward
__device__ float g_Y [MAXB * TLEN * 1024];
__device__ float g_Nm[MAXB * TLEN * 1024];
__device__ float g_Pp[MAXB * TLEN * 1024];
__device__ float g_zp[MAXB * TLEN * 32];

// ---- shared memory layout (float offsets) ----
#define O_SAM  0
#define O_SBM  8192
#define O_SCM  16384
#define O_A    20480   // 32xLD A_t
#define O_ATR  21632   // 32xLD A_t^T
#define O_CM   22784   // 16xLD C_t
#define O_CTR  23360   // 32xLDCT C_t^T
#define O_ZC   24000   // 32xLD covariance state
#define O_TMP  25152   // 32xLD B mixture
#define O_PP   26304   // 32xLD Ppred
#define O_CPM  27456   // 16xLD M
#define O_AUG0 28032   // 32xLDA N staging (fwd)
#define O_AUG1 30208   // fwd: CArm (576) + CNsh (@+1024, 576) ; bwd: W
#define O_AGS0 32384   // 16xLDS2 S-GJ buffer 0
#define O_AGS1 33216   // 16xLDS2 S-GJ buffer 1
#define O_KT2  34048   // 32xLDK Kg
#define O_FCS  34688   // 2 x 1152 filtered cov (parity)
#define O_FMS  36992   // 2 x 32
#define O_YB   37056   // 2 x 1152 Y (parity)
#define O_YT   39360   // 2 x 1152 Y^T (parity)
#define O_NB   41664   // 2 x 1152 N (parity)
#define O_ZPS  43968   // 2 x 32 zpred (parity)
#define O_ZM   44032
#define O_ZM2  44064
#define O_AL   44096   // 2 x 8
#define O_SU   44112   // 2 x 32
#define O_SA   44176   // 2 x 16
#define O_AP   44208   // 16
#define O_DZ   44224   // 32
#define O_QD   44256   // 32
#define O_RD   44288   // 16
#define O_CAT  44304   // 32xLDCT  CA^T
#define O_CQC  44944   // 16xLDCT  C diag(q) C^T
#define SMEM_FLOATS 45264

__device__ __forceinline__ float4 f4fma(float s, float4 b, float4 a) {
    return make_float4(fmaf(s,b.x,a.x), fmaf(s,b.y,a.y), fmaf(s,b.z,a.z), fmaf(s,b.w,a.w));
}
__device__ __forceinline__ float4 f4scale(float4 a, float s) {
    return make_float4(a.x*s, a.y*s, a.z*s, a.w*s);
}
#define FMA4S(acc, s, b)                                                      \
    acc.x = fmaf((s), (b).x, acc.x); acc.y = fmaf((s), (b).y, acc.y);         \
    acc.z = fmaf((s), (b).z, acc.z); acc.w = fmaf((s), (b).w, acc.w);
#define FMA4L(s4, m4, v4)                                                     \
    s4.x = fmaf(m4.x, v4.x, s4.x); s4.y = fmaf(m4.y, v4.y, s4.y);             \
    s4.z = fmaf(m4.z, v4.z, s4.z); s4.w = fmaf(m4.w, v4.w, s4.w);

__device__ __forceinline__ float4 mm4(const float* __restrict__ rowA,
                                      const float* __restrict__ matB,
                                      const int ldB, const int jj) {
    float4 a0 = make_float4(0.f,0.f,0.f,0.f);
    float4 a1 = make_float4(0.f,0.f,0.f,0.f);
    #pragma unroll
    for (int k0 = 0; k0 < 32; k0 += 8) {
        float4 x = *(const float4*)(rowA + k0);
        float4 y = *(const float4*)(rowA + k0 + 4);
        const float* Bp = matB + k0 * ldB + jj;
        float4 b;
        b = *(const float4*)(Bp);           FMA4S(a0, x.x, b);
        b = *(const float4*)(Bp + ldB);     FMA4S(a1, x.y, b);
        b = *(const float4*)(Bp + 2*ldB);   FMA4S(a0, x.z, b);
        b = *(const float4*)(Bp + 3*ldB);   FMA4S(a1, x.w, b);
        b = *(const float4*)(Bp + 4*ldB);   FMA4S(a0, y.x, b);
        b = *(const float4*)(Bp + 5*ldB);   FMA4S(a1, y.y, b);
        b = *(const float4*)(Bp + 6*ldB);   FMA4S(a0, y.z, b);
        b = *(const float4*)(Bp + 7*ldB);   FMA4S(a1, y.w, b);
    }
    return make_float4(a0.x + a1.x, a0.y + a1.y, a0.z + a1.z, a0.w + a1.w);
}

__device__ __forceinline__ void mm24(const float* __restrict__ rA0,
                                     const float* __restrict__ rA1,
                                     const float* __restrict__ matB,
                                     const int ldB, const int jj,
                                     float4& o0, float4& o1) {
    float4 a0 = make_float4(0.f,0.f,0.f,0.f);
    float4 a1 = make_float4(0.f,0.f,0.f,0.f);
    float4 c0 = make_float4(0.f,0.f,0.f,0.f);
    float4 c1 = make_float4(0.f,0.f,0.f,0.f);
    #pragma unroll
    for (int k0 = 0; k0 < 32; k0 += 4) {
        float4 x = *(const float4*)(rA0 + k0);
        float4 y = *(const float4*)(rA1 + k0);
        const float* Bp = matB + k0 * ldB + jj;
        float4 b;
        b = *(const float4*)(Bp);         FMA4S(a0, x.x, b); FMA4S(c0, y.x, b);
        b = *(const float4*)(Bp + ldB);   FMA4S(a1, x.y, b); FMA4S(c1, y.y, b);
        b = *(const float4*)(Bp + 2*ldB); FMA4S(a0, x.z, b); FMA4S(c0, y.z, b);
        b = *(const float4*)(Bp + 3*ldB); FMA4S(a1, x.w, b); FMA4S(c1, y.w, b);
    }
    o0 = make_float4(a0.x+a1.x, a0.y+a1.y, a0.z+a1.z, a0.w+a1.w);
    o1 = make_float4(c0.x+c1.x, c0.y+c1.y, c0.z+c1.z, c0.w+c1.w);
}

// ---- 4-pivot Gauss-Jordan block state (fwd S-solve) ----
struct GJ4 {
    float inv0, inv1, inv2, inv3;
    float P10, P20, P30, a21, a31, a32;
    float c0, c1, c2, c3;
    int p0, gi;
};
__device__ __forceinline__ GJ4 gj4_pre(const float* __restrict__ Asrc, int gi,
                                       int p0, int lda) {
    GJ4 s; s.p0 = p0; s.gi = gi;
    const float4 R0 = *(const float4*)(Asrc + (p0+0)*lda + p0);
    const float4 R1 = *(const float4*)(Asrc + (p0+1)*lda + p0);
    const float4 R2 = *(const float4*)(Asrc + (p0+2)*lda + p0);
    const float4 R3 = *(const float4*)(Asrc + (p0+3)*lda + p0);
    const float4 Ci = *(const float4*)(Asrc + gi*lda + p0);
    s.inv0 = __fdividef(1.f, R0.x);
    float u01 = R0.y*s.inv0, u02 = R0.z*s.inv0, u03 = R0.w*s.inv0;
    s.P10 = R1.x;
    float a11 = fmaf(-R1.x, u01, R1.y);  s.inv1 = __fdividef(1.f, a11);
    float a12 = fmaf(-R1.x, u02, R1.z), a13 = fmaf(-R1.x, u03, R1.w);
    float v12 = a12*s.inv1, v13 = a13*s.inv1;
    s.P20 = R2.x;
    s.a21 = fmaf(-R2.x, u01, R2.y);
    float a22 = fmaf(-s.a21, v12, fmaf(-R2.x, u02, R2.z));
    s.inv2 = __fdividef(1.f, a22);
    float a23 = fmaf(-s.a21, v13, fmaf(-R2.x, u03, R2.w));
    float w23 = a23*s.inv2;
    s.P30 = R3.x;
    s.a31 = fmaf(-R3.x, u01, R3.y);
    s.a32 = fmaf(-s.a31, v12, fmaf(-R3.x, u02, R3.z));
    float a33 = fmaf(-s.a32, w23, fmaf(-s.a31, v13, fmaf(-R3.x, u03, R3.w)));
    s.inv3 = __fdividef(1.f, a33);
    s.c0 = Ci.x;
    s.c1 = (gi==p0)   ? u01 : fmaf(-s.c0, u01, Ci.y);
    float c2t = (gi==p0)   ? u02 : fmaf(-s.c0, u02, Ci.z);
    s.c2 = (gi==p0+1) ? v12 : fmaf(-s.c1, v12, c2t);
    float c3t = (gi==p0)   ? u03 : fmaf(-s.c0, u03, Ci.w);
    float c3u = (gi==p0+1) ? v13 : fmaf(-s.c1, v13, c3t);
    s.c3 = (gi==p0+2) ? w23 : fmaf(-s.c2, w23, c3u);
    return s;
}
__device__ __forceinline__ float4 gj4_col4(const GJ4& s, const float* __restrict__ Asrc,
                                           int jj, int lda) {
    const int p0 = s.p0, gi = s.gi;
    float4 m0 = *(const float4*)(Asrc + (p0+0)*lda + jj);
    float4 m1 = *(const float4*)(Asrc + (p0+1)*lda + jj);
    float4 m2 = *(const float4*)(Asrc + (p0+2)*lda + jj);
    float4 m3 = *(const float4*)(Asrc + (p0+3)*lda + jj);
    float4 mi = *(const float4*)(Asrc + gi*lda + jj);
    float4 r0 = f4scale(m0, s.inv0);
    float4 E  = (gi==p0)   ? r0 : f4fma(-s.c0, r0, mi);
    float4 t1 = f4fma(-s.P10, r0, m1);
    float4 r1 = f4scale(t1, s.inv1);
    E = (gi==p0+1) ? r1 : f4fma(-s.c1, r1, E);
    float4 t2 = f4fma(-s.a21, r1, f4fma(-s.P20, r0, m2));
    float4 r2 = f4scale(t2, s.inv2);
    E = (gi==p0+2) ? r2 : f4fma(-s.c2, r2, E);
    float4 t3 = f4fma(-s.a32, r2, f4fma(-s.a31, r1, f4fma(-s.P30, r0, m3)));
    float4 r3 = f4scale(t3, s.inv3);
    E = (gi==p0+3) ? r3 : f4fma(-s.c3, r3, E);
    return E;
}

// ===================== K1: forward filter =====================
__global__ __launch_bounds__(NT, 1)
void lgssm_fwd(const float* __restrict__ g_a,   const float* __restrict__ g_alpha,
               const float* __restrict__ g_u,   const float* __restrict__ g_A,
               const float* __restrict__ g_B,   const float* __restrict__ g_C,
               const float* __restrict__ g_lQ,  const float* __restrict__ g_lR,
               const float* __restrict__ g_z0m, const float* __restrict__ g_z0lv,
               float* __restrict__ out)
{
    extern __shared__ float sh[];
    float* sAm  = sh + O_SAM;
    float* sBm  = sh + O_SBM;
    float* sCm  = sh + O_SCM;
    float* pA   = sh + O_A;
    float* pAtr = sh + O_ATR;
    float* pCm  = sh + O_CM;
    float* pCtr = sh + O_CTR;
    float* zc   = sh + O_ZC;
    float* tmpM = sh + O_TMP;
    float* pPp  = sh + O_PP;
    float* pCPm = sh + O_CPM;
    float* aug0 = sh + O_AUG0;
    float* CArm = sh + O_AUG1;          // 16xLD
    float* CNsh = sh + O_AUG1 + 1024;   // 16xLD
    float* augS0= sh + O_AGS0;
    float* augS1= sh + O_AGS1;
    float* KT2  = sh + O_KT2;
    float* zm   = sh + O_ZM;
    float* zm2  = sh + O_ZM2;
    float* alB  = sh + O_AL;
    float* suB  = sh + O_SU;
    float* saB  = sh + O_SA;
    float* apred= sh + O_AP;
    float* dz   = sh + O_DZ;
    float* qd   = sh + O_QD;
    float* rd   = sh + O_RD;
    float* CAtr = sh + O_CAT;
    float* CQC  = sh + O_CQC;

    const int tid = threadIdx.x;
    const int b   = blockIdx.x;
    const int i4  = tid >> 3;          // 0..31 for tid<256
    const int j4  = (tid & 7) << 2;

    for (int idx = tid; idx < 8192; idx += NT) sAm[idx] = g_A[idx];
    for (int idx = tid; idx < 8192; idx += NT) sBm[idx] = g_B[idx];
    for (int idx = tid; idx < 4096; idx += NT) sCm[idx] = g_C[idx];
    if (tid < 32) qd[tid] = expf(g_lQ[tid]);
    if (tid < 16) rd[tid] = expf(g_lR[tid]);
    {
        const size_t ib0 = (size_t)b * TLEN;
        if (tid < 8)  alB[tid] = g_alpha[ib0 * 8  + tid];
        if (tid < 32) suB[tid] = g_u    [ib0 * 32 + tid];
        if (tid < 16) saB[tid] = g_a    [ib0 * 16 + tid];
        if (tid < 32) { zm[tid] = g_z0m[tid]; zm2[tid] = g_z0m[tid]; }
        if (tid < 256) {
            float4 v = make_float4(0.f, 0.f, 0.f, 0.f);
            int d = i4 - j4;
            if (d >= 0 && d < 4) ((float*)&v)[d] = expf(g_z0lv[i4]);
            *(float4*)(pPp + i4 * LD + j4) = v;   // Ppred at t=0 = prior cov
        }
    }
    __syncthreads();

    // prolog: mixtures for t=0 (A,B on [0,256); C on [256,384))
    if (tid < 256) {
        float4 aa = make_float4(0.f,0.f,0.f,0.f);
        float4 bb = make_float4(0.f,0.f,0.f,0.f);
        #pragma unroll
        for (int k = 0; k < 8; ++k) {
            const float w = alB[k];
            float4 m = *(const float4*)(sAm + k * 1024 + i4 * 32 + j4);
            FMA4S(aa, w, m);
            m = *(const float4*)(sBm + k * 1024 + i4 * 32 + j4);
            FMA4S(bb, w, m);
        }
        *(float4*)(pA + i4 * LD + j4) = aa;
        pAtr[(j4+0)*LD + i4] = aa.x; pAtr[(j4+1)*LD + i4] = aa.y;
        pAtr[(j4+2)*LD + i4] = aa.z; pAtr[(j4+3)*LD + i4] = aa.w;
        *(float4*)(tmpM + i4 * LD + j4) = bb;
    } else if (tid < 384) {
        const int idx = tid - 256;
        const int ci = idx >> 3, cj = (idx & 7) << 2;
        float4 cc = make_float4(0.f,0.f,0.f,0.f);
        #pragma unroll
        for (int k = 0; k < 8; ++k) {
            const float w = alB[k];
            float4 m = *(const float4*)(sCm + k * 512 + ci * 32 + cj);
            FMA4S(cc, w, m);
        }
        *(float4*)(pCm + ci * LD + cj) = cc;
        pCtr[(cj+0)*LDCT + ci] = cc.x; pCtr[(cj+1)*LDCT + ci] = cc.y;
        pCtr[(cj+2)*LDCT + ci] = cc.z; pCtr[(cj+3)*LDCT + ci] = cc.w;
    }
    __syncthreads();

    #pragma unroll 1
    for (int t = 0; t < TLEN; ++t) {
        const size_t ib = (size_t)b * TLEN + t;
        const int pb = t & 1, nb = pb ^ 1;
        const bool hasnext = (t + 1 < TLEN);

        // prefetch next step's inputs (threads 448-503; stored at F2)
        float pfa = 0.f, pfu = 0.f, pfo = 0.f;
        if (hasnext && tid >= 448) {
            if (tid < 456)      pfa = g_alpha[(ib + 1) * 8  + (tid - 448)];
            else if (tid < 472) pfo = g_a    [(ib + 1) * 16 + (tid - 456)];
            else if (tid < 504) pfu = g_u    [(ib + 1) * 32 + (tid - 472)];
        }

        // ---- F1: N = A·zc (+STG) || CN = CA·zc || zpred (+STG) ----
        if (t > 0) {
            if (tid < 256) {
                float4 n = mm4(pA + i4 * LD, zc, LD, j4);
                *(float4*)(aug0 + i4 * LDA + 32 + j4) = n;
                *(float4*)(g_Nm + (ib-1)*1024 + i4 * 32 + j4) = n;
            } else if (tid < 384) {
                const int idx = tid - 256;
                const int ci = idx >> 3, cj = (idx & 7) << 2;
                float4 cn = mm4(CArm + ci*LD, zc, LD, cj);
                *(float4*)(CNsh + ci*LD + cj) = cn;
            } else if (tid >= 480) {
                const int i = tid - 480;
                const float* su = suB + pb * 32;
                float4 s4 = make_float4(0.f,0.f,0.f,0.f);
                #pragma unroll
                for (int k0 = 0; k0 < 32; k0 += 4) {
                    float4 m4 = *(const float4*)(tmpM + i * LD + k0);
                    float4 v4 = *(const float4*)(su + k0);
                    FMA4L(s4, m4, v4);
                    m4 = *(const float4*)(pA + i * LD + k0);
                    v4 = *(const float4*)(zm + k0);
                    FMA4L(s4, m4, v4);
                }
                float zp = (s4.x + s4.y) + (s4.z + s4.w);
                zm2[i] = zp;
                g_zp[(ib - 1) * 32 + i] = zp;
            }
        }
        __syncthreads();

        // ---- F2: Ppred (+STG) || M || S || apred || prefetch stores ----
        if (t > 0) {
            if (tid < 256) {
                float4 p = mm4(aug0 + i4 * LDA + 32, pAtr, LD, j4);
                int d = i4 - j4;
                if (d >= 0 && d < 4) ((float*)&p)[d] += qd[i4];
                *(float4*)(pPp + i4 * LD + j4) = p;
                *(float4*)(g_Pp + (ib-1)*1024 + i4 * 32 + j4) = p;
            } else if (tid < 384) {
                const int idx = tid - 256;
                const int ci = idx >> 3, cj = (idx & 7) << 2;
                float4 m = mm4(CNsh + ci*LD, pAtr, LD, cj);
                float4 c4 = *(const float4*)(pCm + ci*LD + cj);
                float4 q4 = *(const float4*)(qd + cj);
                m.x = fmaf(c4.x, q4.x, m.x); m.y = fmaf(c4.y, q4.y, m.y);
                m.z = fmaf(c4.z, q4.z, m.z); m.w = fmaf(c4.w, q4.w, m.w);
                *(float4*)(pCPm + ci*LD + cj) = m;
                *(float4*)(augS0 + ci*LDS2 + 16 + cj) = m;
            } else if (tid < 448) {
                const int idx = tid - 384;
                const int si = idx >> 2, sj = (idx & 3) << 2;
                float4 s = mm4(CNsh + si*LD, CAtr, LDCT, sj);
                float4 cq = *(const float4*)(CQC + si*LDCT + sj);
                s.x += cq.x; s.y += cq.y; s.z += cq.z; s.w += cq.w;
                int d = si - sj;
                if (d >= 0 && d < 4) ((float*)&s)[d] += rd[si];
                *(float4*)(augS0 + si*LDS2 + sj) = s;
            }
        } else {
            if (tid >= 256 && tid < 384) {
                const int idx = tid - 256;
                const int ci = idx >> 3, cj = (idx & 7) << 2;
                float4 m = mm4(pCm + ci*LD, pPp, LD, cj);
                *(float4*)(pCPm + ci*LD + cj) = m;
                *(float4*)(augS0 + ci*LDS2 + 16 + cj) = m;
            }
        }
        if (tid >= 448 && tid < 464) {
            const int i = tid - 448;
            float4 s4 = make_float4(0.f,0.f,0.f,0.f);
            #pragma unroll
            for (int k0 = 0; k0 < 32; k0 += 4) {
                float4 m4 = *(const float4*)(pCm + i * LD + k0);
                float4 v4 = *(const float4*)(zm2 + k0);
                FMA4L(s4, m4, v4);
            }
            apred[i] = (s4.x + s4.y) + (s4.z + s4.w);
        }
        if (hasnext && tid >= 448) {
            if (tid < 456)      alB[nb*8  + (tid-448)] = pfa;
            else if (tid < 472) saB[nb*16 + (tid-456)] = pfo;
            else if (tid < 504) suB[nb*32 + (tid-472)] = pfu;
        }
        __syncthreads();

        if (t == 0) {   // extra phase: build S from M (only once)
            if (tid < 64) {
                const int si = tid >> 2, sj = (tid & 3) << 2;
                float4 s = mm4(pCPm + si*LD, pCtr, LDCT, sj);
                int d = si - sj;
                if (d >= 0 && d < 4) ((float*)&s)[d] += rd[si];
                *(float4*)(augS0 + si*LDS2 + sj) = s;
            }
            __syncthreads();
        }

        // ---- S0..S3: S-solve (thr<192) + dz + next mixtures/CA/CQC ----
        #pragma unroll
        for (int sp = 0; sp < 4; ++sp) {
            if (tid < 192) {
                const int si = tid & 15;
                const int sj = (tid >> 4) << 2;
                float* Ss = (sp & 1) ? augS1 : augS0;
                float* Sd = (sp & 1) ? augS0 : augS1;
                if (sp < 3 || sj >= 16) {
                    GJ4 s = gj4_pre(Ss, si, sp << 2, LDS2);
                    float4 E = gj4_col4(s, Ss, sj, LDS2);
                    if (sp < 3) {
                        *(float4*)(Sd + si * LDS2 + sj) = E;
                    } else {
                        KT2[(sj-16+0)*LDK + si] = E.x;
                        KT2[(sj-16+1)*LDK + si] = E.y;
                        KT2[(sj-16+2)*LDK + si] = E.z;
                        KT2[(sj-16+3)*LDK + si] = E.w;
                    }
                }
            } else if (sp == 0) {
                if (tid < 208) {
                    const int j = tid - 192;
                    dz[j] = saB[pb * 16 + j] - apred[j];
                } else if (hasnext && tid < 464) {
                    const int cell = tid - 208;
                    const int ri = cell >> 3, jj = (cell & 7) << 2;
                    const float* al = alB + nb * 8;
                    float4 aa = make_float4(0.f,0.f,0.f,0.f);
                    float4 bb = make_float4(0.f,0.f,0.f,0.f);
                    #pragma unroll
                    for (int k = 0; k < 8; ++k) {
                        const float w = al[k];
                        float4 m = *(const float4*)(sAm + k * 1024 + ri * 32 + jj);
                        FMA4S(aa, w, m);
                        m = *(const float4*)(sBm + k * 1024 + ri * 32 + jj);
                        FMA4S(bb, w, m);
                    }
                    *(float4*)(pA + ri * LD + jj) = aa;
                    pAtr[(jj+0)*LD + ri] = aa.x; pAtr[(jj+1)*LD + ri] = aa.y;
                    pAtr[(jj+2)*LD + ri] = aa.z; pAtr[(jj+3)*LD + ri] = aa.w;
                    *(float4*)(tmpM + ri * LD + jj) = bb;
                }
            } else if (sp == 1) {
                if (hasnext && tid >= 208 && tid < 336) {
                    const int cell = tid - 208;
                    const int ci = cell >> 3, cj = (cell & 7) << 2;
                    const float* al = alB + nb * 8;
                    float4 cc = make_float4(0.f,0.f,0.f,0.f);
                    #pragma unroll
                    for (int k = 0; k < 8; ++k) {
                        const float w = al[k];
                        float4 m = *(const float4*)(sCm + k * 512 + ci * 32 + cj);
                        FMA4S(cc, w, m);
                    }
                    *(float4*)(pCm + ci * LD + cj) = cc;
                    pCtr[(cj+0)*LDCT + ci] = cc.x; pCtr[(cj+1)*LDCT + ci] = cc.y;
                    pCtr[(cj+2)*LDCT + ci] = cc.z; pCtr[(cj+3)*LDCT + ci] = cc.w;
                }
            } else if (sp == 2) {
                if (hasnext && tid >= 208 && tid < 336) {
                    const int cell = tid - 208;
                    const int ci = cell >> 3, cj = (cell & 7) << 2;
                    float4 ca = mm4(pCm + ci*LD, pA, LD, cj);
                    *(float4*)(CArm + ci*LD + cj) = ca;
                    CAtr[(cj+0)*LDCT + ci] = ca.x; CAtr[(cj+1)*LDCT + ci] = ca.y;
                    CAtr[(cj+2)*LDCT + ci] = ca.z; CAtr[(cj+3)*LDCT + ci] = ca.w;
                }
            } else {   // sp == 3
                if (hasnext && tid >= 208 && tid < 272) {
                    const int cell = tid - 208;
                    const int qi = cell >> 2, qj = (cell & 3) << 2;
                    float4 acc = make_float4(0.f,0.f,0.f,0.f);
                    #pragma unroll
                    for (int k0 = 0; k0 < 32; k0 += 4) {
                        float4 c4 = *(const float4*)(pCm + qi*LD + k0);
                        float4 q4 = *(const float4*)(qd + k0);
                        float4 bq;
                        bq = *(const float4*)(pCtr + (k0+0)*LDCT + qj); FMA4S(acc, c4.x*q4.x, bq);
                        bq = *(const float4*)(pCtr + (k0+1)*LDCT + qj); FMA4S(acc, c4.y*q4.y, bq);
                        bq = *(const float4*)(pCtr + (k0+2)*LDCT + qj); FMA4S(acc, c4.z*q4.z, bq);
                        bq = *(const float4*)(pCtr + (k0+3)*LDCT + qj); FMA4S(acc, c4.w*q4.w, bq);
                    }
                    *(float4*)(CQC + qi*LDCT + qj) = acc;
                }
            }
            __syncthreads();
        }

        // ---- F7: measurement update + filtered output ----
        {
            const size_t ob = ib * 2112;
            if (tid < 256) {
                float4 acc = *(const float4*)(pPp + i4*LD + j4);
                #pragma unroll
                for (int rr = 0; rr < 16; rr += 4) {
                    float4 k4 = *(const float4*)(KT2 + i4*LDK + rr);
                    float4 m;
                    m = *(const float4*)(pCPm + (rr+0)*LD + j4); acc = f4fma(-k4.x, m, acc);
                    m = *(const float4*)(pCPm + (rr+1)*LD + j4); acc = f4fma(-k4.y, m, acc);
                    m = *(const float4*)(pCPm + (rr+2)*LD + j4); acc = f4fma(-k4.z, m, acc);
                    m = *(const float4*)(pCPm + (rr+3)*LD + j4); acc = f4fma(-k4.w, m, acc);
                }
                *(float4*)(zc + i4*LD + j4) = acc;
                *(float4*)(out + ob + 32 + i4*32 + j4) = acc;
                if (t == TLEN - 1) *(float4*)(out + ob + 1088 + i4*32 + j4) = acc;
            } else if (tid >= 480) {
                const int i = tid - 480;
                float4 s4 = make_float4(0.f,0.f,0.f,0.f);
                #pragma unroll
                for (int rr = 0; rr < 16; rr += 4) {
                    float4 k4 = *(const float4*)(KT2 + i * LDK + rr);
                    float4 d4 = *(const float4*)(dz + rr);
                    FMA4L(s4, k4, d4);
                }
                float nm = zm2[i] + (s4.x + s4.y) + (s4.z + s4.w);
                zm[i] = nm;
                out[ob + i] = nm;
                if (t == TLEN - 1) out[ob + 1056 + i] = nm;
            }
        }
        __syncthreads();
    }
}

// ===================== K2: batched Y-solves (register + shuffle) ==========
// one warp per solve; lane owns columns `lane` (Ppred) and `lane+32` (N).
// fully unrolled 32-pivot Gauss-Jordan, dead left columns pruned (lane > p).
__global__ __launch_bounds__(256, 2)
void lgssm_ysolve(int nsolve)
{
    const int wid  = (blockIdx.x << 3) + (threadIdx.x >> 5);
    const int lane = threadIdx.x & 31;
    if (wid >= nsolve) return;
    const int bb = wid / (TLEN - 1);
    const int ss = wid % (TLEN - 1);
    const size_t slot = (size_t)bb * TLEN + ss;

    float cL[32], cR[32];
    const float* Pp = g_Pp + slot * 1024;
    const float* Nm = g_Nm + slot * 1024;
    #pragma unroll
    for (int i = 0; i < 32; ++i) {
        cL[i] = Pp[i * 32 + lane];
        cR[i] = Nm[i * 32 + lane];
    }

    const unsigned full = 0xffffffffu;
    #pragma unroll
    for (int p = 0; p < 32; ++p) {
        float pivd = __shfl_sync(full, cL[p], p);
        float inv  = __fdividef(1.f, pivd);
        float rL = cL[p] * inv;
        float rR = cR[p] * inv;
        const bool updL = (lane > p);
        #pragma unroll
        for (int i = 0; i < 32; ++i) {
            if (i != p) {
                float cp = __shfl_sync(full, cL[i], p);
                if (updL) cL[i] = fmaf(-cp, rL, cL[i]);
                cR[i] = fmaf(-cp, rR, cR[i]);
            }
        }
        if (updL) cL[p] = rL;
        cR[p] = rR;
    }

    float* Y = g_Y + slot * 1024;
    #pragma unroll
    for (int i = 0; i < 32; ++i)
        Y[i * 32 + lane] = cR[i];
}

// ===================== K3: backward smoother =====================
__global__ __launch_bounds__(NT, 1)
void lgssm_bwd(float* __restrict__ out)
{
    extern __shared__ float sh[];
    float* aug1 = sh + O_AUG1;
    float* fcS  = sh + O_FCS;
    float* fmS  = sh + O_FMS;
    float* Ybuf = sh + O_YB;
    float* YtrB = sh + O_YT;
    float* NbS  = sh + O_NB;
    float* zpS  = sh + O_ZPS;
    float* zm   = sh + O_ZM;
    float* zm2  = sh + O_ZM2;
    float* zc   = sh + O_ZC;

    const int tid = threadIdx.x;
    const int b   = blockIdx.x;
    const int i4  = tid >> 3;
    const int j4  = (tid & 7) << 2;
    const int r0  = tid >> 3;
    const int r1  = r0 + 16;

    {   // init state + preload slot TLEN-2 into parity 0
        const size_t obL   = ((size_t)b * TLEN + (TLEN - 1)) * 2112;
        const size_t slot0 = (size_t)b * TLEN + (TLEN - 2);
        if (tid < 32) zm[tid] = out[obL + tid];
        if (tid < 256) {
            *(float4*)(zc + i4 * LD + j4) =
                *(const float4*)(out + obL + 32 + i4 * 32 + j4);
            float4 y = *(const float4*)(g_Y  + slot0 * 1024 + i4 * 32 + j4);
            float4 n = *(const float4*)(g_Nm + slot0 * 1024 + i4 * 32 + j4);
            *(float4*)(Ybuf + i4 * LD + j4) = y;
            YtrB[(j4+0)*LD + i4] = y.x; YtrB[(j4+1)*LD + i4] = y.y;
            YtrB[(j4+2)*LD + i4] = y.z; YtrB[(j4+3)*LD + i4] = y.w;
            *(float4*)(NbS + i4 * LD + j4) = n;
            *(float4*)(fcS + i4 * LD + j4) =
                *(const float4*)(out + slot0 * 2112 + 32 + i4 * 32 + j4);
        }
        if (tid < 32) {
            zpS[tid] = g_zp[slot0 * 32 + tid];
            fmS[tid] = out[slot0 * 2112 + tid];
        }
    }
    __syncthreads();

    #pragma unroll 1
    for (int t = TLEN - 2; t >= 0; --t) {
        const size_t ib = (size_t)b * TLEN + t;
        const size_t ob = ib * 2112;
        const int pb = t & 1;
        const int nb = pb ^ 1;
        const bool hasprev = (t > 0);

        float4 pfY = make_float4(0.f,0.f,0.f,0.f);
        float4 pfN = make_float4(0.f,0.f,0.f,0.f);
        float4 pfc = make_float4(0.f,0.f,0.f,0.f);
        float pfz = 0.f, pfm = 0.f;
        int pi = 0, pj = 0;
        if (tid >= 256) { const int idx = tid - 256; pi = idx >> 3; pj = (idx & 7) << 2; }
        if (hasprev) {
            const size_t sp = ib - 1;
            if (tid >= 256) {
                pfY = *(const float4*)(g_Y  + sp * 1024 + pi * 32 + pj);
                pfN = *(const float4*)(g_Nm + sp * 1024 + pi * 32 + pj);
                pfc = *(const float4*)(out + sp * 2112 + 32 + pi * 32 + pj);
            }
            if (tid >= 448 && tid < 480) {
                pfz = g_zp[sp * 32 + (tid - 448)];
                pfm = out[sp * 2112 + (tid - 448)];
            }
        }

        // ---- PW: W = Ps·Y - N (128 thr) ; zs2 (warp 15) ----
        if (tid < 128) {
            float4 o0, o1;
            mm24(zc + r0*LD, zc + r1*LD, Ybuf + pb*1152, LD, j4, o0, o1);
            float4 n0 = *(const float4*)(NbS + pb*1152 + r0*LD + j4);
            float4 n1 = *(const float4*)(NbS + pb*1152 + r1*LD + j4);
            o0.x -= n0.x; o0.y -= n0.y; o0.z -= n0.z; o0.w -= n0.w;
            o1.x -= n1.x; o1.y -= n1.y; o1.z -= n1.z; o1.w -= n1.w;
            *(float4*)(aug1 + r0*LDA + j4) = o0;
            *(float4*)(aug1 + r1*LDA + j4) = o1;
        } else if (tid >= 480) {
            const int i = tid - 480;
            float4 s4 = make_float4(0.f,0.f,0.f,0.f);
            #pragma unroll
            for (int k0 = 0; k0 < 32; k0 += 4) {
                float4 y4 = *(const float4*)(YtrB + pb*1152 + i*LD + k0);
                float4 z4 = *(const float4*)(zm + k0);
                float4 p4 = *(const float4*)(zpS + pb*32 + k0);
                float4 d4 = make_float4(z4.x-p4.x, z4.y-p4.y, z4.z-p4.z, z4.w-p4.w);
                FMA4L(s4, y4, d4);
            }
            zm2[i] = fmS[pb*32 + i] + (s4.x + s4.y) + (s4.z + s4.w);
        }
        __syncthreads();

        // ---- P21: Ps = fc + Ytr·W ; outputs ; store prefetch [nb] ----
        if (tid < 128) {
            float4 w0, w1;
            mm24(YtrB + pb*1152 + r0*LD, YtrB + pb*1152 + r1*LD, aug1, LDA, j4, w0, w1);
            float4 f0 = *(const float4*)(fcS + pb*1152 + r0*LD + j4);
            float4 f1 = *(const float4*)(fcS + pb*1152 + r1*LD + j4);
            f0.x += w0.x; f0.y += w0.y; f0.z += w0.z; f0.w += w0.w;
            f1.x += w1.x; f1.y += w1.y; f1.z += w1.z; f1.w += w1.w;
            *(float4*)(zc + r0*LD + j4) = f0;
            *(float4*)(zc + r1*LD + j4) = f1;
            *(float4*)(out + ob + 1088 + r0*32 + j4) = f0;
            *(float4*)(out + ob + 1088 + r1*32 + j4) = f1;
        }
        if (tid >= 256 && hasprev) {
            *(float4*)(Ybuf + nb*1152 + pi*LD + pj) = pfY;
            YtrB[nb*1152 + (pj+0)*LD + pi] = pfY.x;
            YtrB[nb*1152 + (pj+1)*LD + pi] = pfY.y;
            YtrB[nb*1152 + (pj+2)*LD + pi] = pfY.z;
            YtrB[nb*1152 + (pj+3)*LD + pi] = pfY.w;
            *(float4*)(NbS + nb*1152 + pi*LD + pj) = pfN;
            *(float4*)(fcS + nb*1152 + pi*LD + pj) = pfc;
        }
        if (tid >= 448 && tid < 480) {
            const int i = tid - 448;
            float nm = zm2[i];
            zm[i] = nm;
            out[ob + 1056 + i] = nm;
            if (hasprev) {
                zpS[nb*32 + i] = pfz;
                fmS[nb*32 + i] = pfm;
            }
        }
        __syncthreads();
    }
}

extern "C" void kernel_launch(void* const* d_in, const int* in_sizes, int n_in,
                              void* d_out, int out_size) {
    const float* g_a    = (const float*)d_in[0];
    const float* g_alpha= (const float*)d_in[1];
    const float* g_u    = (const float*)d_in[2];
    const float* g_Ai   = (const float*)d_in[3];
    const float* g_Bi   = (const float*)d_in[4];
    const float* g_Ci   = (const float*)d_in[5];
    const float* g_lQ   = (const float*)d_in[6];
    const float* g_lR   = (const float*)d_in[7];
    const float* g_z0m  = (const float*)d_in[8];
    const float* g_z0lv = (const float*)d_in[9];
    float* out = (float*)d_out;
    int B = in_sizes[0] / (TLEN * 16);
    size_t smem = SMEM_FLOATS * sizeof(float);
    cudaFuncSetAttribute(lgssm_fwd, cudaFuncAttributeMaxDynamicSharedMemorySize, (int)smem);
    cudaFuncSetAttribute(lgssm_bwd, cudaFuncAttributeMaxDynamicSharedMemorySize, (int)smem);
    lgssm_fwd<<<B, NT, smem>>>(g_a, g_alpha, g_u, g_Ai, g_Bi, g_Ci,
                               g_lQ, g_lR, g_z0m, g_z0lv, out);
    int nsolve = B * (TLEN - 1);
    int grid2 = (nsolve + 7) / 8;
    lgssm_ysolve<<<grid2, 256>>>(nsolve);
    lgssm_bwd<<<B, NT, smem>>>(out);
}